// round 13
// baseline (speedup 1.0000x reference)
#include <cuda_runtime.h>
#include <cuda_fp16.h>
#include <cstdint>
#include <cstddef>

#define SEQn 2048
#define Bn   64
#define In   256
#define Hn   256
#define G3n  768
#define TBn  32
#define NBLKn 64
#define MR   8192
#define MI   131072    // SEQ*B

#define NT   256       // 8 warps: 2(m) x 4(n)
#define ASTH 40
#define BSTH 264
#define A_STAGE_H (128 * ASTH)
#define MT_PER_CTA 16

// input_gemm smem (R11, proven)
#define IG_B_OFF_H (3 * A_STAGE_H)
#define IG_SMEM ((IG_B_OFF_H + 96 * BSTH) * 2)

// phase v3 smem layout (units: halfs)
#define HBSTH 264                       // h buffer row stride (proven conflict-free)
#define PB_ST 40                        // B stage row stride (proven conflict-free)
#define GXST 200                        // GX buffer row stride
#define H0_OFF 0
#define H1_OFF (64 * HBSTH)             // 16896
#define PB_OFF (2 * 64 * HBSTH)         // 33792
#define PB_STAGE (192 * PB_ST)          // 7680
#define GX0_OFF (PB_OFF + 4 * PB_STAGE) // 64512
#define GX1_OFF (GX0_OFF + 64 * GXST)   // 77312
#define PH_SMEM ((GX1_OFF + 64 * GXST) * 2)   // 180224 B

#define NCTA_P 128
#define NCHUNK_TOT (64 * 32)

__device__ __half g_GX[(size_t)2 * MI * G3n];
__device__ __half g_X16[(size_t)MI * In];
__device__ __half g_Wih16[(size_t)2 * G3n * In];
__device__ __half g_Whh16[(size_t)2 * G3n * Hn];
__device__ __half g_End16[(size_t)MR * Hn];   // prescaled block-end carries
__device__ unsigned g_barc;
__device__ unsigned g_barg;

static __device__ __forceinline__ void mma16(float c[4], const uint32_t a[4],
                                             uint32_t b0, uint32_t b1) {
    asm volatile(
        "mma.sync.aligned.m16n8k16.row.col.f32.f16.f16.f32 "
        "{%0,%1,%2,%3}, {%4,%5,%6,%7}, {%8,%9}, {%0,%1,%2,%3};\n"
        : "+f"(c[0]), "+f"(c[1]), "+f"(c[2]), "+f"(c[3])
        : "r"(a[0]), "r"(a[1]), "r"(a[2]), "r"(a[3]), "r"(b0), "r"(b1));
}

#define LDSM4(r, addr) \
    asm volatile("ldmatrix.sync.aligned.m8n8.x4.shared.b16 {%0,%1,%2,%3}, [%4];" \
                 : "=r"((r)[0]), "=r"((r)[1]), "=r"((r)[2]), "=r"((r)[3]) : "r"(addr))

static __device__ __forceinline__ void cpasync16(uint32_t dst, const void* src, int srcsize) {
    asm volatile("cp.async.cg.shared.global [%0], [%1], 16, %2;\n"
                 :: "r"(dst), "l"(src), "r"(srcsize));
}
#define CP_COMMIT() asm volatile("cp.async.commit_group;\n" ::: "memory")
#define CP_WAIT1()  asm volatile("cp.async.wait_group 1;\n" ::: "memory")
#define CP_WAIT2()  asm volatile("cp.async.wait_group 2;\n" ::: "memory")

// ---------------------------------------------------------------------------
#define NX4 ((size_t)MI * In / 4)
#define NW4 ((size_t)G3n * In / 4)

__global__ void convert_all(const float* __restrict__ X,
                            const float* __restrict__ Wih_f, const float* __restrict__ Wih_b,
                            const float* __restrict__ Whh_f, const float* __restrict__ Whh_b)
{
    size_t i = (size_t)blockIdx.x * blockDim.x + threadIdx.x;
    const float* src; __half* dst; size_t off;
    if (i < NX4)                { src = X;     dst = g_X16;              off = i; }
    else if (i < NX4 + NW4)     { src = Wih_f; dst = g_Wih16;            off = i - NX4; }
    else if (i < NX4 + 2 * NW4) { src = Wih_b; dst = g_Wih16 + G3n * In; off = i - NX4 - NW4; }
    else if (i < NX4 + 3 * NW4) { src = Whh_f; dst = g_Whh16;            off = i - NX4 - 2 * NW4; }
    else if (i < NX4 + 4 * NW4) { src = Whh_b; dst = g_Whh16 + G3n * Hn; off = i - NX4 - 3 * NW4; }
    else return;
    float4 v = reinterpret_cast<const float4*>(src)[off];
    reinterpret_cast<__half2*>(dst)[2 * off]     = __floats2half2_rn(v.x, v.y);
    reinterpret_cast<__half2*>(dst)[2 * off + 1] = __floats2half2_rn(v.z, v.w);
}

// ---------------------------------------------------------------------------
// Input GEMM (R11, unchanged): resident Wih slice + 16 streamed m-tiles.
// ---------------------------------------------------------------------------
__global__ void __launch_bounds__(NT, 2)
input_gemm(const float* __restrict__ bih_f, const float* __restrict__ bhh_f,
           const float* __restrict__ bih_b, const float* __restrict__ bhh_b)
{
    extern __shared__ __half smh[];
    const uint32_t smA_u = (uint32_t)__cvta_generic_to_shared(smh);
    const uint32_t smB_u = smA_u + IG_B_OFF_H * 2;
    __half* smB = smh + IG_B_OFF_H;

    const int tid = threadIdx.x;
    const int warp = tid >> 5, lane = tid & 31;
    const int wm = warp >> 2, wn = warp & 3;
    const int lane8 = lane & 7, laneB = lane >> 3;

    const int c0 = blockIdx.x * 32;
    const size_t mbase = (size_t)blockIdx.y * (MT_PER_CTA * 128);
    const int dir = blockIdx.z;

    const float* bih = dir ? bih_b : bih_f;
    const float* bhh = dir ? bhh_b : bhh_f;

    {
        const __half* Wt = g_Wih16 + (size_t)dir * G3n * In;
        for (int idx = tid; idx < 96 * 32; idx += NT) {
            int row = idx >> 5, seg = (idx & 31) * 8;
            const float4 v = *reinterpret_cast<const float4*>(
                Wt + (size_t)((row >> 5) * Hn + c0 + (row & 31)) * In + seg);
            *reinterpret_cast<float4*>(smB + row * BSTH + seg) = v;
        }
    }
    __syncthreads();

    int a_off[4], b_off[3];
    #pragma unroll
    for (int mf = 0; mf < 4; mf++)
        a_off[mf] = (wm * 64 + mf * 16 + lane8 + 8 * (laneB & 1)) * ASTH + 8 * (lane >> 4);
    #pragma unroll
    for (int gt = 0; gt < 3; gt++)
        b_off[gt] = (gt * 32 + wn * 8 + lane8) * BSTH + 8 * laneB;

    const int aRow = tid >> 2, aChk = (tid & 3) * 8;
    const int g = lane >> 2, tk = lane & 3;
    const int colb = c0 + wn * 8 + 2 * tk;

    float bias[3][2];
    #pragma unroll
    for (int gt = 0; gt < 3; gt++) {
        int gcol = gt * Hn + colb;
        bias[gt][0] = bih[gcol]     + (gt < 2 ? bhh[gcol]     : 0.f);
        bias[gt][1] = bih[gcol + 1] + (gt < 2 ? bhh[gcol + 1] : 0.f);
    }

    __half* GXd = g_GX + (size_t)dir * MI * G3n;

    auto issueA = [&](int c) {
        const uint32_t base = smA_u + (c % 3) * (A_STAGE_H * 2);
        const int kco = (c & 7) * 32;
        const __half* s = g_X16 + (mbase + (size_t)(c >> 3) * 128 + aRow) * In + kco + aChk;
        cpasync16(base + (uint32_t)(aRow * ASTH + aChk) * 2, s, 16);
        cpasync16(base + (uint32_t)((aRow + 64) * ASTH + aChk) * 2, s + (size_t)64 * In, 16);
    };

    issueA(0); CP_COMMIT();
    issueA(1); CP_COMMIT();

    const int NCHUNK = MT_PER_CTA * 8;
    #pragma unroll 1
    for (int mt = 0; mt < MT_PER_CTA; mt++) {
        float acc[3][4][4];
        #pragma unroll
        for (int gt = 0; gt < 3; gt++)
            #pragma unroll
            for (int mi = 0; mi < 4; mi++)
                #pragma unroll
                for (int q = 0; q < 4; q++) acc[gt][mi][q] = 0.f;

        #pragma unroll 1
        for (int kc = 0; kc < 8; kc++) {
            const int c = mt * 8 + kc;
            CP_WAIT1();
            __syncthreads();
            if (c + 2 < NCHUNK) issueA(c + 2);
            CP_COMMIT();

            const uint32_t Ab = smA_u + (c % 3) * (A_STAGE_H * 2);

            uint32_t bfr[3][4];
            #pragma unroll
            for (int gt = 0; gt < 3; gt++)
                LDSM4(bfr[gt], smB_u + (uint32_t)(kc * 32 + b_off[gt]) * 2);
            #pragma unroll
            for (int ks = 0; ks < 2; ks++) {
                #pragma unroll
                for (int mf = 0; mf < 4; mf++) {
                    uint32_t af[4];
                    LDSM4(af, Ab + (a_off[mf] + 16 * ks) * 2);
                    #pragma unroll
                    for (int gt = 0; gt < 3; gt++)
                        mma16(acc[gt][mf], af, bfr[gt][2 * ks], bfr[gt][2 * ks + 1]);
                }
            }
        }

        const size_t m0 = mbase + (size_t)mt * 128;
        #pragma unroll
        for (int gt = 0; gt < 3; gt++) {
            int gcol = gt * Hn + colb;
            #pragma unroll
            for (int mi = 0; mi < 4; mi++) {
                size_t r0 = m0 + (size_t)(wm * 64 + mi * 16 + g);
                *reinterpret_cast<__half2*>(GXd + r0 * G3n + gcol) =
                    __floats2half2_rn(acc[gt][mi][0] + bias[gt][0], acc[gt][mi][1] + bias[gt][1]);
                *reinterpret_cast<__half2*>(GXd + (r0 + 8) * G3n + gcol) =
                    __floats2half2_rn(acc[gt][mi][2] + bias[gt][0], acc[gt][mi][3] + bias[gt][1]);
            }
        }
    }
}

// ---------------------------------------------------------------------------
static __device__ __forceinline__ float
row_scale(int rg, int j, int dir, const int* __restrict__ D)
{
    int blk = (rg >> 6) & 63, b = rg & 63;
    int t = dir ? (blk * TBn + TBn - 1 - j) : (blk * TBn + j);
    int m = dir ? ((t == SEQn - 1) ? 0 : D[(t + 1) * Bn + b]) : D[t * Bn + b];
    return 1.f - (float)m;
}

static __device__ __forceinline__ void bar_sync(unsigned* cnt, unsigned* gen, unsigned n)
{
    __threadfence();
    __syncthreads();
    if (threadIdx.x == 0) {
        unsigned gv = *(volatile unsigned*)gen;
        unsigned c = atomicAdd(cnt, 1u);
        if (c == n - 1) {
            atomicExch(cnt, 0u);
            __threadfence();
            atomicAdd(gen, 1u);
        } else {
            while (*(volatile unsigned*)gen == gv) { __nanosleep(32); }
        }
    }
    __syncthreads();
    __threadfence();
}

// ---------------------------------------------------------------------------
// Phase v3: CTA = (dir, blk). h lives in smem (double-buffered); no per-step
// barriers; B streamed from L2 with 4-stage pipeline; GX prefetched one pass
// ahead. One global barrier at the round boundary (End handoff).
// ---------------------------------------------------------------------------
__global__ void __launch_bounds__(NT, 1)
phase_persistent(const int* __restrict__ D,
                 const float* __restrict__ bhh_f, const float* __restrict__ bhh_b,
                 float* __restrict__ out)
{
    extern __shared__ __half smh[];
    const uint32_t sm_u = (uint32_t)__cvta_generic_to_shared(smh);

    const int tid = threadIdx.x;
    const int warp = tid >> 5, lane = tid & 31;
    const int wm = warp >> 2, wn = warp & 3;
    const int lane8 = lane & 7, laneB = lane >> 3;
    const int g = lane >> 2, tk = lane & 3;

    const int cta = blockIdx.x;
    const int dir = cta >> 6;
    const int blk = cta & 63;
    const int rg0 = dir * 4096 + blk * 64;

    const __half* Wt  = g_Whh16 + (size_t)dir * G3n * Hn;
    const __half* GXd = g_GX + (size_t)dir * MI * G3n;
    const float* bhh = dir ? bhh_b : bhh_f;

    // zero h buffer 0 (initial state; pads included)
    for (int i = tid; i < 64 * HBSTH / 2; i += NT)
        reinterpret_cast<uint32_t*>(smh)[i] = 0;
    __syncthreads();

    int a_off[2];
    #pragma unroll
    for (int mf = 0; mf < 2; mf++)
        a_off[mf] = (wm * 32 + mf * 16 + lane8 + 8 * (laneB & 1)) * HBSTH + 8 * (lane >> 4);
    int b_off[3][2];
    #pragma unroll
    for (int gt = 0; gt < 3; gt++)
        #pragma unroll
        for (int nf = 0; nf < 2; nf++)
            b_off[gt][nf] = (gt * 64 + wn * 16 + nf * 8 + lane8) * PB_ST + 8 * laneB;

    auto issueB = [&](int c) {
        int cpos = c & 31, p = cpos >> 3, kc = cpos & 7;
        uint32_t base = sm_u + (uint32_t)(PB_OFF + (c & 3) * PB_STAGE) * 2;
        #pragma unroll
        for (int s = 0; s < 3; s++) {
            int idx = tid + NT * s;
            int row = idx >> 2, piece = idx & 3;
            int gt = row >> 6, cl = row & 63;
            const __half* src = Wt + (size_t)(gt * Hn + p * 64 + cl) * Hn + kc * 32 + piece * 8;
            cpasync16(base + (uint32_t)(row * PB_ST + piece * 8) * 2, src, 16);
        }
    };
    auto issueGX = [&](int gp, int si) {
        if (gp >= 256) return;
        int p = gp & 3, step = gp >> 2;
        int j = step & 31;
        int t = dir ? (blk * TBn + TBn - 1 - j) : (blk * TBn + j);
        int idx = si * NT + tid;                 // 0..1535
        int row = idx / 24, piece = idx - row * 24;
        int gcol = (piece >> 3) * Hn + p * 64 + (piece & 7) * 8;
        uint32_t base = sm_u + (uint32_t)((gp & 1) ? GX1_OFF : GX0_OFF) * 2;
        cpasync16(base + (uint32_t)(row * GXST + piece * 8) * 2,
                  GXd + (size_t)(t * Bn + row) * G3n + gcol, 16);
    };

    // prologue: B chunks 0..2, GX pass 0
    issueB(0); issueGX(0, 0); issueGX(0, 1); issueGX(0, 2); CP_COMMIT();
    issueB(1); issueGX(0, 3); issueGX(0, 4); issueGX(0, 5); CP_COMMIT();
    issueB(2); CP_COMMIT();

    int c = 0;
    #pragma unroll 1
    for (int step = 0; step < 2 * TBn; step++) {
        const int rnd = step >> 5, j = step & 31;
        const int t = dir ? (blk * TBn + TBn - 1 - j) : (blk * TBn + j);
        const uint32_t hbA_u = sm_u + (uint32_t)((step & 1) ? H1_OFF : H0_OFF) * 2;
        __half* hA = smh + ((step & 1) ? H1_OFF : H0_OFF);
        __half* hN = smh + ((step & 1) ? H0_OFF : H1_OFF);

        if (step == TBn) {
            bar_sync(&g_barc, &g_barg, NCTA_P);
            // reload hA with prescaled carries from the neighbor block's End
            int nb = dir ? blk + 1 : blk - 1;
            bool valid = (nb >= 0 && nb < NBLKn);
            const __half* src = g_End16 + (size_t)(dir * 4096 + nb * 64) * Hn;
            #pragma unroll
            for (int s = 0; s < 8; s++) {
                int idx = tid + NT * s;          // 0..2047 -> 64 rows x 32 pieces
                int row = idx >> 5, col8 = (idx & 31) * 8;
                float4 v = make_float4(0.f, 0.f, 0.f, 0.f);
                if (valid)
                    v = *reinterpret_cast<const float4*>(src + (size_t)row * Hn + col8);
                *reinterpret_cast<float4*>(hA + row * HBSTH + col8) = v;
            }
            __syncthreads();
        }

        #pragma unroll 1
        for (int p = 0; p < 4; p++) {
            const int gp = step * 4 + p;
            float acc[3][2][2][4];
            #pragma unroll
            for (int gt = 0; gt < 3; gt++)
                #pragma unroll
                for (int mf = 0; mf < 2; mf++)
                    #pragma unroll
                    for (int nf = 0; nf < 2; nf++)
                        #pragma unroll
                        for (int q = 0; q < 4; q++) acc[gt][mf][nf][q] = 0.f;

            #pragma unroll 1
            for (int kc = 0; kc < 8; kc++, c++) {
                CP_WAIT2();
                __syncthreads();
                if (c + 3 < NCHUNK_TOT) issueB(c + 3);
                if (kc < 6) issueGX(gp + 1, kc);
                CP_COMMIT();

                const uint32_t Bs = sm_u + (uint32_t)(PB_OFF + (c & 3) * PB_STAGE) * 2;
                uint32_t bfr[3][2][4];
                #pragma unroll
                for (int gt = 0; gt < 3; gt++)
                    #pragma unroll
                    for (int nf = 0; nf < 2; nf++)
                        LDSM4(bfr[gt][nf], Bs + (uint32_t)b_off[gt][nf] * 2);

                #pragma unroll
                for (int ks = 0; ks < 2; ks++) {
                    #pragma unroll
                    for (int mf = 0; mf < 2; mf++) {
                        uint32_t af[4];
                        LDSM4(af, hbA_u + (uint32_t)(a_off[mf] + kc * 32 + 16 * ks) * 2);
                        #pragma unroll
                        for (int gt = 0; gt < 3; gt++)
                            #pragma unroll
                            for (int nf = 0; nf < 2; nf++)
                                mma16(acc[gt][mf][nf], af,
                                      bfr[gt][nf][2 * ks], bfr[gt][nf][2 * ks + 1]);
                    }
                }
            }

            // ---- epilogue for pass p ----
            const __half* gxs = smh + ((gp & 1) ? GX1_OFF : GX0_OFF);
            #pragma unroll
            for (int mf = 0; mf < 2; mf++) {
                #pragma unroll
                for (int pr = 0; pr < 2; pr++) {
                    int row = wm * 32 + mf * 16 + g + 8 * pr;
                    int rg = rg0 + row;
                    #pragma unroll
                    for (int nf = 0; nf < 2; nf++) {
                        int cl = wn * 16 + nf * 8 + 2 * tk;
                        int hcolg = p * 64 + cl;

                        float2 hu = __half22float2(
                            *reinterpret_cast<const __half2*>(hA + row * HBSTH + hcolg));
                        float2 gr = __half22float2(
                            *reinterpret_cast<const __half2*>(gxs + row * GXST + cl));
                        float2 gz = __half22float2(
                            *reinterpret_cast<const __half2*>(gxs + row * GXST + 64 + cl));
                        float2 gn = __half22float2(
                            *reinterpret_cast<const __half2*>(gxs + row * GXST + 128 + cl));
                        float2 bn2 = *reinterpret_cast<const float2*>(bhh + 2 * Hn + hcolg);

                        float a_r0 = acc[0][mf][nf][2 * pr], a_r1 = acc[0][mf][nf][2 * pr + 1];
                        float a_z0 = acc[1][mf][nf][2 * pr], a_z1 = acc[1][mf][nf][2 * pr + 1];
                        float a_n0 = acc[2][mf][nf][2 * pr], a_n1 = acc[2][mf][nf][2 * pr + 1];

                        float rv0 = 1.f / (1.f + __expf(-(gr.x + a_r0)));
                        float rv1 = 1.f / (1.f + __expf(-(gr.y + a_r1)));
                        float zv0 = 1.f / (1.f + __expf(-(gz.x + a_z0)));
                        float zv1 = 1.f / (1.f + __expf(-(gz.y + a_z1)));
                        float nv0 = tanhf(gn.x + rv0 * (a_n0 + bn2.x));
                        float nv1 = tanhf(gn.y + rv1 * (a_n1 + bn2.y));
                        float h0 = (1.f - zv0) * nv0 + zv0 * hu.x;
                        float h1 = (1.f - zv1) * nv1 + zv1 * hu.y;

                        if (j < TBn - 1) {
                            float wsc = row_scale(rg, j + 1, dir, D);
                            *reinterpret_cast<__half2*>(hN + row * HBSTH + hcolg) =
                                __floats2half2_rn(h0 * wsc, h1 * wsc);
                        } else if (rnd == 0) {
                            int rgc = rg + (dir ? -Bn : Bn);
                            bool v2 = dir ? (blk > 0) : (blk < NBLKn - 1);
                            float wsc = v2 ? row_scale(rgc, 0, dir, D) : 0.f;
                            *reinterpret_cast<__half2*>(g_End16 + (size_t)rg * Hn + hcolg) =
                                __floats2half2_rn(h0 * wsc, h1 * wsc);
                        }
                        if (rnd == 1)
                            *reinterpret_cast<float2*>(
                                out + (size_t)(t * Bn + row) * (2 * Hn) + dir * Hn + hcolg) =
                                make_float2(h0, h1);
                    }
                }
            }
        }
    }
}

// ---------------------------------------------------------------------------
extern "C" void kernel_launch(void* const* d_in, const int* in_sizes, int n_in,
                              void* d_out, int out_size)
{
    const float* X     = (const float*)d_in[0];
    const int*   D     = (const int*)d_in[1];
    const float* Wih_f = (const float*)d_in[2];
    const float* Whh_f = (const float*)d_in[3];
    const float* bih_f = (const float*)d_in[4];
    const float* bhh_f = (const float*)d_in[5];
    const float* Wih_b = (const float*)d_in[6];
    const float* Whh_b = (const float*)d_in[7];
    const float* bih_b = (const float*)d_in[8];
    const float* bhh_b = (const float*)d_in[9];
    float* out = (float*)d_out;

    cudaFuncSetAttribute(input_gemm, cudaFuncAttributeMaxDynamicSharedMemorySize, IG_SMEM);
    cudaFuncSetAttribute(phase_persistent, cudaFuncAttributeMaxDynamicSharedMemorySize, PH_SMEM);

    const size_t ntot = NX4 + 4 * NW4;
    convert_all<<<(unsigned)((ntot + 255) / 256), 256>>>(X, Wih_f, Wih_b, Whh_f, Whh_b);

    input_gemm<<<dim3(Hn / 32, MI / (MT_PER_CTA * 128), 2), NT, IG_SMEM>>>(
        bih_f, bhh_f, bih_b, bhh_b);

    phase_persistent<<<NCTA_P, NT, PH_SMEM>>>(D, bhh_f, bhh_b, out);
}

// round 14
// speedup vs baseline: 1.1244x; 1.1244x over previous
#include <cuda_runtime.h>
#include <cuda_fp16.h>
#include <cstdint>
#include <cstddef>

#define SEQn 2048
#define Bn   64
#define In   256
#define Hn   256
#define G3n  768
#define TBn  32
#define NBLKn 64
#define MR   8192
#define MI   131072

#define NT   256       // 8 warps: 2(m) x 4(n)
#define ASTH 40
#define BSTH 264
#define GXSTH 104
#define A_STAGE_H (128 * ASTH)
#define NCTA 256
#define NMP  32
#define MT_PER_CTA 16

#define IG_B_OFF_H (3 * A_STAGE_H)
#define IG_SMEM ((IG_B_OFF_H + 96 * BSTH) * 2)

#define PP_B_OFF_H  (3 * A_STAGE_H)
#define PP_GX_OFF_H (PP_B_OFF_H + 96 * BSTH)
#define PP_SMEM ((PP_GX_OFF_H + 128 * GXSTH) * 2)   // 108032 B

__device__ __half g_GX[(size_t)2 * MI * G3n];
__device__ __half g_X16[(size_t)MI * In];
__device__ __half g_Wih16[(size_t)2 * G3n * In];
__device__ __half g_Whh16[(size_t)2 * G3n * Hn];
__device__ __half g_State16[2][(size_t)MR * Hn];
__device__ __half g_End16[(size_t)MR * Hn];
__device__ unsigned g_barc;
__device__ unsigned g_barg;
__device__ unsigned g_lbc[NMP];
__device__ unsigned g_lbg[NMP];

static __device__ __forceinline__ void mma16(float c[4], const uint32_t a[4],
                                             uint32_t b0, uint32_t b1) {
    asm volatile(
        "mma.sync.aligned.m16n8k16.row.col.f32.f16.f16.f32 "
        "{%0,%1,%2,%3}, {%4,%5,%6,%7}, {%8,%9}, {%0,%1,%2,%3};\n"
        : "+f"(c[0]), "+f"(c[1]), "+f"(c[2]), "+f"(c[3])
        : "r"(a[0]), "r"(a[1]), "r"(a[2]), "r"(a[3]), "r"(b0), "r"(b1));
}

#define LDSM4(r, addr) \
    asm volatile("ldmatrix.sync.aligned.m8n8.x4.shared.b16 {%0,%1,%2,%3}, [%4];" \
                 : "=r"((r)[0]), "=r"((r)[1]), "=r"((r)[2]), "=r"((r)[3]) : "r"(addr))

static __device__ __forceinline__ void cpasync16(uint32_t dst, const void* src, int srcsize) {
    asm volatile("cp.async.cg.shared.global [%0], [%1], 16, %2;\n"
                 :: "r"(dst), "l"(src), "r"(srcsize));
}
#define CP_COMMIT() asm volatile("cp.async.commit_group;\n" ::: "memory")
#define CP_WAIT1()  asm volatile("cp.async.wait_group 1;\n" ::: "memory")

// ---------------------------------------------------------------------------
// no-op launch: shifts ncu's capture index so launch #5 == phase_persistent
__global__ void noop_kernel() {}

// ---------------------------------------------------------------------------
#define NX4 ((size_t)MI * In / 4)
#define NW4 ((size_t)G3n * In / 4)

__global__ void convert_all(const float* __restrict__ X,
                            const float* __restrict__ Wih_f, const float* __restrict__ Wih_b,
                            const float* __restrict__ Whh_f, const float* __restrict__ Whh_b)
{
    size_t i = (size_t)blockIdx.x * blockDim.x + threadIdx.x;
    const float* src; __half* dst; size_t off;
    if (i < NX4)                { src = X;     dst = g_X16;              off = i; }
    else if (i < NX4 + NW4)     { src = Wih_f; dst = g_Wih16;            off = i - NX4; }
    else if (i < NX4 + 2 * NW4) { src = Wih_b; dst = g_Wih16 + G3n * In; off = i - NX4 - NW4; }
    else if (i < NX4 + 3 * NW4) { src = Whh_f; dst = g_Whh16;            off = i - NX4 - 2 * NW4; }
    else if (i < NX4 + 4 * NW4) { src = Whh_b; dst = g_Whh16 + G3n * Hn; off = i - NX4 - 3 * NW4; }
    else return;
    float4 v = reinterpret_cast<const float4*>(src)[off];
    reinterpret_cast<__half2*>(dst)[2 * off]     = __floats2half2_rn(v.x, v.y);
    reinterpret_cast<__half2*>(dst)[2 * off + 1] = __floats2half2_rn(v.z, v.w);
}

// ---------------------------------------------------------------------------
// Input GEMM (R11, unchanged): resident Wih slice + 16 streamed m-tiles.
// ---------------------------------------------------------------------------
__global__ void __launch_bounds__(NT, 2)
input_gemm(const float* __restrict__ bih_f, const float* __restrict__ bhh_f,
           const float* __restrict__ bih_b, const float* __restrict__ bhh_b)
{
    extern __shared__ __half smh[];
    const uint32_t smA_u = (uint32_t)__cvta_generic_to_shared(smh);
    const uint32_t smB_u = smA_u + IG_B_OFF_H * 2;
    __half* smB = smh + IG_B_OFF_H;

    const int tid = threadIdx.x;
    const int warp = tid >> 5, lane = tid & 31;
    const int wm = warp >> 2, wn = warp & 3;
    const int lane8 = lane & 7, laneB = lane >> 3;

    const int c0 = blockIdx.x * 32;
    const size_t mbase = (size_t)blockIdx.y * (MT_PER_CTA * 128);
    const int dir = blockIdx.z;

    const float* bih = dir ? bih_b : bih_f;
    const float* bhh = dir ? bhh_b : bhh_f;

    {
        const __half* Wt = g_Wih16 + (size_t)dir * G3n * In;
        for (int idx = tid; idx < 96 * 32; idx += NT) {
            int row = idx >> 5, seg = (idx & 31) * 8;
            const float4 v = *reinterpret_cast<const float4*>(
                Wt + (size_t)((row >> 5) * Hn + c0 + (row & 31)) * In + seg);
            *reinterpret_cast<float4*>(smB + row * BSTH + seg) = v;
        }
    }
    __syncthreads();

    int a_off[4], b_off[3];
    #pragma unroll
    for (int mf = 0; mf < 4; mf++)
        a_off[mf] = (wm * 64 + mf * 16 + lane8 + 8 * (laneB & 1)) * ASTH + 8 * (lane >> 4);
    #pragma unroll
    for (int gt = 0; gt < 3; gt++)
        b_off[gt] = (gt * 32 + wn * 8 + lane8) * BSTH + 8 * laneB;

    const int aRow = tid >> 2, aChk = (tid & 3) * 8;
    const int g = lane >> 2, tk = lane & 3;
    const int colb = c0 + wn * 8 + 2 * tk;

    float bias[3][2];
    #pragma unroll
    for (int gt = 0; gt < 3; gt++) {
        int gcol = gt * Hn + colb;
        bias[gt][0] = bih[gcol]     + (gt < 2 ? bhh[gcol]     : 0.f);
        bias[gt][1] = bih[gcol + 1] + (gt < 2 ? bhh[gcol + 1] : 0.f);
    }

    __half* GXd = g_GX + (size_t)dir * MI * G3n;

    auto issueA = [&](int c) {
        const uint32_t base = smA_u + (c % 3) * (A_STAGE_H * 2);
        const int kco = (c & 7) * 32;
        const __half* s = g_X16 + (mbase + (size_t)(c >> 3) * 128 + aRow) * In + kco + aChk;
        cpasync16(base + (uint32_t)(aRow * ASTH + aChk) * 2, s, 16);
        cpasync16(base + (uint32_t)((aRow + 64) * ASTH + aChk) * 2, s + (size_t)64 * In, 16);
    };

    issueA(0); CP_COMMIT();
    issueA(1); CP_COMMIT();

    const int NCHUNK = MT_PER_CTA * 8;
    #pragma unroll 1
    for (int mt = 0; mt < MT_PER_CTA; mt++) {
        float acc[3][4][4];
        #pragma unroll
        for (int gt = 0; gt < 3; gt++)
            #pragma unroll
            for (int mi = 0; mi < 4; mi++)
                #pragma unroll
                for (int q = 0; q < 4; q++) acc[gt][mi][q] = 0.f;

        #pragma unroll 1
        for (int kc = 0; kc < 8; kc++) {
            const int c = mt * 8 + kc;
            CP_WAIT1();
            __syncthreads();
            if (c + 2 < NCHUNK) issueA(c + 2);
            CP_COMMIT();

            const uint32_t Ab = smA_u + (c % 3) * (A_STAGE_H * 2);

            uint32_t bfr[3][4];
            #pragma unroll
            for (int gt = 0; gt < 3; gt++)
                LDSM4(bfr[gt], smB_u + (uint32_t)(kc * 32 + b_off[gt]) * 2);
            #pragma unroll
            for (int ks = 0; ks < 2; ks++) {
                #pragma unroll
                for (int mf = 0; mf < 4; mf++) {
                    uint32_t af[4];
                    LDSM4(af, Ab + (a_off[mf] + 16 * ks) * 2);
                    #pragma unroll
                    for (int gt = 0; gt < 3; gt++)
                        mma16(acc[gt][mf], af, bfr[gt][2 * ks], bfr[gt][2 * ks + 1]);
                }
            }
        }

        const size_t m0 = mbase + (size_t)mt * 128;
        #pragma unroll
        for (int gt = 0; gt < 3; gt++) {
            int gcol = gt * Hn + colb;
            #pragma unroll
            for (int mi = 0; mi < 4; mi++) {
                size_t r0 = m0 + (size_t)(wm * 64 + mi * 16 + g);
                *reinterpret_cast<__half2*>(GXd + r0 * G3n + gcol) =
                    __floats2half2_rn(acc[gt][mi][0] + bias[gt][0], acc[gt][mi][1] + bias[gt][1]);
                *reinterpret_cast<__half2*>(GXd + (r0 + 8) * G3n + gcol) =
                    __floats2half2_rn(acc[gt][mi][2] + bias[gt][0], acc[gt][mi][3] + bias[gt][1]);
            }
        }
    }
}

// ---------------------------------------------------------------------------
static __device__ __forceinline__ float
row_scale(int rg, int j, int dir, const int* __restrict__ D)
{
    int blk = (rg >> 6) & 63, b = rg & 63;
    int t = dir ? (blk * TBn + TBn - 1 - j) : (blk * TBn + j);
    int m = dir ? ((t == SEQn - 1) ? 0 : D[(t + 1) * Bn + b]) : D[t * Bn + b];
    return 1.f - (float)m;
}

static __device__ __forceinline__ const __half*
row_src(int rg, int j, int rnd, int dir, const __half* Sread)
{
    if (j > 0) return Sread + (size_t)rg * Hn;
    if (rnd == 1) {
        int blk = (rg >> 6) & 63;
        int nb = dir ? blk + 1 : blk - 1;
        if (nb >= 0 && nb < NBLKn)
            return g_End16 + (size_t)(rg + (dir ? Bn : -Bn)) * Hn;
    }
    return nullptr;
}

static __device__ __forceinline__ void bar_sync(unsigned* cnt, unsigned* gen, unsigned n)
{
    __threadfence();
    __syncthreads();
    if (threadIdx.x == 0) {
        unsigned gv = *(volatile unsigned*)gen;
        unsigned c = atomicAdd(cnt, 1u);
        if (c == n - 1) {
            atomicExch(cnt, 0u);
            __threadfence();
            atomicAdd(gen, 1u);
        } else {
            while (*(volatile unsigned*)gen == gv) { __nanosleep(32); }
        }
    }
    __syncthreads();
    __threadfence();
}

// ---------------------------------------------------------------------------
// Persistent phase kernel (R9/R11 structure) + pre-barrier GX prefetch for
// the next step's mt0 (GX is barrier-independent).
// ---------------------------------------------------------------------------
__global__ void __launch_bounds__(NT, 2)
phase_persistent(const int* __restrict__ D,
                 const float* __restrict__ bhh_f, const float* __restrict__ bhh_b,
                 float* __restrict__ out)
{
    extern __shared__ __half smh[];
    const uint32_t smA_u = (uint32_t)__cvta_generic_to_shared(smh);
    const uint32_t smB_u = smA_u + PP_B_OFF_H * 2;
    const uint32_t smGX_u = smA_u + PP_GX_OFF_H * 2;
    __half* smB  = smh + PP_B_OFF_H;
    __half* smGX = smh + PP_GX_OFF_H;

    const int tid = threadIdx.x;
    const int warp = tid >> 5, lane = tid & 31;
    const int wm = warp >> 2, wn = warp & 3;
    const int lane8 = lane & 7, laneB = lane >> 3;

    const int cta = blockIdx.x;
    const int mpair = cta >> 3;
    const int c0 = (cta & 7) * 32;
    const int kch = cta & 7;
    const int m0base = mpair * 256;
    const int dir = m0base >> 12;

    const float* bhh = dir ? bhh_b : bhh_f;

    {
        const __half* Wt = g_Whh16 + (size_t)dir * G3n * Hn;
        for (int idx = tid; idx < 96 * 32; idx += NT) {
            int row = idx >> 5, seg = (idx & 31) * 8;
            const float4 v = *reinterpret_cast<const float4*>(
                Wt + (size_t)((row >> 5) * Hn + c0 + (row & 31)) * Hn + seg);
            *reinterpret_cast<float4*>(smB + row * BSTH + seg) = v;
        }
    }
    __syncthreads();

    int a_off[4], b_off[3];
    #pragma unroll
    for (int mf = 0; mf < 4; mf++)
        a_off[mf] = (wm * 64 + mf * 16 + lane8 + 8 * (laneB & 1)) * ASTH + 8 * (lane >> 4);
    #pragma unroll
    for (int gt = 0; gt < 3; gt++)
        b_off[gt] = (gt * 32 + wn * 8 + lane8) * BSTH + 8 * laneB;

    const int aRow = tid >> 2, aChk = (tid & 3) * 8;
    const int g = lane >> 2, tk = lane & 3;
    const int lc = wn * 8 + 2 * tk;
    const int colb = c0 + lc;
    const float2 bn2 = *reinterpret_cast<const float2*>(bhh + 2 * Hn + colb);

    const int gxrow = tid & 127;
    const int gxp0 = tid >> 7;
    const __half* GXd = g_GX + (size_t)dir * MI * G3n;

    // issue ALL 6 mt0 GX pieces for a given step (barrier-independent)
    auto gx_issue_mt0 = [&](int step) {
        int j = step & 31;
        int rg = m0base + gxrow;
        int blk = (rg >> 6) & 63, b = rg & 63;
        int t = dir ? (blk * TBn + TBn - 1 - j) : (blk * TBn + j);
        const __half* src = GXd + (size_t)(t * Bn + b) * G3n;
        #pragma unroll
        for (int s = 0; s < 6; s++) {
            int p = gxp0 + 2 * s;
            cpasync16(smGX_u + (uint32_t)(gxrow * GXSTH + p * 8) * 2,
                      src + (p >> 2) * Hn + c0 + (p & 3) * 8, 16);
        }
    };

    // step 0 mt0 GX (smGX untouched yet; Whh-load syncthreads already done)
    gx_issue_mt0(0); CP_COMMIT();

    for (int step = 0; step < 2 * TBn; step++) {
        const int rnd = step >> 5, j = step & 31, cur = step & 1;
        if (step == TBn)  bar_sync(&g_barc, &g_barg, NCTA);
        else if (step)    bar_sync(&g_lbc[mpair], &g_lbg[mpair], 8);

        __half* Swrite16 = g_State16[cur ^ 1];

        const __half* sA[2][2];
        const __half* gxsrc1;
        #pragma unroll
        for (int mt = 0; mt < 2; mt++) {
            sA[mt][0] = row_src(m0base + mt * 128 + aRow,      j, rnd, dir, g_State16[cur]);
            sA[mt][1] = row_src(m0base + mt * 128 + aRow + 64, j, rnd, dir, g_State16[cur]);
        }
        {
            int rg = m0base + 128 + gxrow;
            int blk = (rg >> 6) & 63, b = rg & 63;
            int t = dir ? (blk * TBn + TBn - 1 - j) : (blk * TBn + j);
            gxsrc1 = GXd + (size_t)(t * Bn + b) * G3n;
        }

        auto issueA = [&](int c) {
            const uint32_t base = smA_u + (c % 3) * (A_STAGE_H * 2);
            const int kco = (c & 7) * 32;
            const __half* s0 = sA[c >> 3][0];
            const __half* s1 = sA[c >> 3][1];
            const __half* dummy = g_Whh16;
            cpasync16(base + (uint32_t)(aRow * ASTH + aChk) * 2,
                      s0 ? s0 + kco + aChk : dummy, s0 ? 16 : 0);
            cpasync16(base + (uint32_t)((aRow + 64) * ASTH + aChk) * 2,
                      s1 ? s1 + kco + aChk : dummy, s1 ? 16 : 0);
        };
        auto issueGX1 = [&](int s) {
            int p = gxp0 + 2 * s;
            cpasync16(smGX_u + (uint32_t)(gxrow * GXSTH + p * 8) * 2,
                      gxsrc1 + (p >> 2) * Hn + c0 + (p & 3) * 8, 16);
        };

        issueA(0); CP_COMMIT();
        issueA(1); CP_COMMIT();

        #pragma unroll 1
        for (int mt = 0; mt < 2; mt++) {
            float acc[3][4][4];
            #pragma unroll
            for (int gt = 0; gt < 3; gt++)
                #pragma unroll
                for (int mi = 0; mi < 4; mi++)
                    #pragma unroll
                    for (int q = 0; q < 4; q++) acc[gt][mi][q] = 0.f;

            __half2 hureg[8];

            #pragma unroll 1
            for (int kc = 0; kc < 8; kc++) {
                const int c = mt * 8 + kc;
                CP_WAIT1();
                __syncthreads();
                if (c + 2 < 16) issueA(c + 2);
                if (c >= 8 && c < 14) issueGX1(c - 8);
                CP_COMMIT();

                const uint32_t Ab = smA_u + (c % 3) * (A_STAGE_H * 2);
                const __half* Ah = smh + (c % 3) * A_STAGE_H;
                const uint32_t Bk = smB_u + (uint32_t)(kc * 32) * 2;

                if (kc == kch) {
                    #pragma unroll
                    for (int q = 0; q < 8; q++) {
                        int row = wm * 64 + (q >> 1) * 16 + g + 8 * (q & 1);
                        hureg[q] = *reinterpret_cast<const __half2*>(Ah + row * ASTH + lc);
                    }
                }

                uint32_t bfr[3][4];
                #pragma unroll
                for (int gt = 0; gt < 3; gt++) LDSM4(bfr[gt], Bk + b_off[gt] * 2);
                #pragma unroll
                for (int ks = 0; ks < 2; ks++) {
                    #pragma unroll
                    for (int mf = 0; mf < 4; mf++) {
                        uint32_t af[4];
                        LDSM4(af, Ab + (a_off[mf] + 16 * ks) * 2);
                        #pragma unroll
                        for (int gt = 0; gt < 3; gt++)
                            mma16(acc[gt][mf], af, bfr[gt][2 * ks], bfr[gt][2 * ks + 1]);
                    }
                }
            }

            const int m0 = m0base + mt * 128;
            #pragma unroll
            for (int mi = 0; mi < 4; mi++) {
                #pragma unroll
                for (int p = 0; p < 2; p++) {
                    int row = wm * 64 + mi * 16 + g + 8 * p;
                    int rg = m0 + row;
                    int blk = (rg >> 6) & 63, b = rg & 63;
                    int t = dir ? (blk * TBn + TBn - 1 - j) : (blk * TBn + j);
                    int tb = t * Bn + b;

                    float2 hu = __half22float2(hureg[mi * 2 + p]);

                    const __half* gxs = smGX + row * GXSTH;
                    float2 gr = __half22float2(*reinterpret_cast<const __half2*>(gxs + lc));
                    float2 gz = __half22float2(*reinterpret_cast<const __half2*>(gxs + 32 + lc));
                    float2 gn = __half22float2(*reinterpret_cast<const __half2*>(gxs + 64 + lc));

                    float rv0 = 1.f / (1.f + __expf(-(gr.x + acc[0][mi][2 * p])));
                    float rv1 = 1.f / (1.f + __expf(-(gr.y + acc[0][mi][2 * p + 1])));
                    float zv0 = 1.f / (1.f + __expf(-(gz.x + acc[1][mi][2 * p])));
                    float zv1 = 1.f / (1.f + __expf(-(gz.y + acc[1][mi][2 * p + 1])));
                    float nv0 = tanhf(gn.x + rv0 * (acc[2][mi][2 * p] + bn2.x));
                    float nv1 = tanhf(gn.y + rv1 * (acc[2][mi][2 * p + 1] + bn2.y));
                    float h0 = (1.f - zv0) * nv0 + zv0 * hu.x;
                    float h1 = (1.f - zv1) * nv1 + zv1 * hu.y;

                    if (j < TBn - 1) {
                        float wsc = row_scale(rg, j + 1, dir, D);
                        *reinterpret_cast<__half2*>(Swrite16 + (size_t)rg * Hn + colb) =
                            __floats2half2_rn(h0 * wsc, h1 * wsc);
                    } else if (rnd == 0) {
                        int rgc = rg + (dir ? -Bn : Bn);
                        bool valid = dir ? (blk > 0) : (blk < NBLKn - 1);
                        float wsc = valid ? row_scale(rgc, 0, dir, D) : 0.f;
                        *reinterpret_cast<__half2*>(g_End16 + (size_t)rg * Hn + colb) =
                            __floats2half2_rn(h0 * wsc, h1 * wsc);
                    }
                    if (rnd == 1)
                        *reinterpret_cast<float2*>(out + (size_t)tb * (2 * Hn) + dir * Hn + colb) =
                            make_float2(h0, h1);
                }
            }
        }

        // pre-barrier GX prefetch for next step's mt0 (overlaps barrier latency)
        if (step + 1 < 2 * TBn) {
            __syncthreads();                  // close mt1 epilogue's smGX reads
            gx_issue_mt0(step + 1);
            CP_COMMIT();
        }
    }
}

// ---------------------------------------------------------------------------
extern "C" void kernel_launch(void* const* d_in, const int* in_sizes, int n_in,
                              void* d_out, int out_size)
{
    const float* X     = (const float*)d_in[0];
    const int*   D     = (const int*)d_in[1];
    const float* Wih_f = (const float*)d_in[2];
    const float* Whh_f = (const float*)d_in[3];
    const float* bih_f = (const float*)d_in[4];
    const float* bhh_f = (const float*)d_in[5];
    const float* Wih_b = (const float*)d_in[6];
    const float* Whh_b = (const float*)d_in[7];
    const float* bih_b = (const float*)d_in[8];
    const float* bhh_b = (const float*)d_in[9];
    float* out = (float*)d_out;

    cudaFuncSetAttribute(input_gemm, cudaFuncAttributeMaxDynamicSharedMemorySize, IG_SMEM);
    cudaFuncSetAttribute(phase_persistent, cudaFuncAttributeMaxDynamicSharedMemorySize, PP_SMEM);

    noop_kernel<<<1, 32>>>();   // shifts ncu capture index onto phase_persistent

    const size_t ntot = NX4 + 4 * NW4;
    convert_all<<<(unsigned)((ntot + 255) / 256), 256>>>(X, Wih_f, Wih_b, Whh_f, Whh_b);

    input_gemm<<<dim3(Hn / 32, MI / (MT_PER_CTA * 128), 2), NT, IG_SMEM>>>(
        bih_f, bhh_f, bih_b, bhh_b);

    phase_persistent<<<NCTA, NT, PP_SMEM>>>(D, bhh_f, bhh_b, out);
}

// round 15
// speedup vs baseline: 1.2198x; 1.0849x over previous
#include <cuda_runtime.h>
#include <cuda_fp16.h>
#include <cstdint>
#include <cstddef>

#define SEQn 2048
#define Bn   64
#define In   256
#define Hn   256
#define G3n  768
#define TBn  32
#define NBLKn 64
#define MR   8192
#define MI   131072

#define NT   256       // 8 warps: 2(m) x 4(n)
#define ASTH 40
#define BSTH 264
#define GXSTH 104
#define A_STAGE_H (128 * ASTH)
#define NCTA 256
#define NMP  32
#define MT_PER_CTA 16

#define IG_B_OFF_H (3 * A_STAGE_H)
#define IG_SMEM ((IG_B_OFF_H + 96 * BSTH) * 2)

#define PP_B_OFF_H  (3 * A_STAGE_H)
#define PP_GX_OFF_H (PP_B_OFF_H + 96 * BSTH)
#define PP_SC_OFF_H (PP_GX_OFF_H + 128 * GXSTH)      // 256 floats = 512 halfs
#define PP_SMEM ((PP_SC_OFF_H + 512) * 2)            // 109056 B

__device__ __half g_GX[(size_t)2 * MI * G3n];
__device__ __half g_X16[(size_t)MI * In];
__device__ __half g_Wih16[(size_t)2 * G3n * In];
__device__ __half g_Whh16[(size_t)2 * G3n * Hn];
__device__ __half g_State16[2][(size_t)MR * Hn];
__device__ __half g_End16[(size_t)MR * Hn];
__device__ unsigned g_barc;
__device__ unsigned g_barg;
__device__ unsigned g_lbc[NMP];
__device__ unsigned g_lbg[NMP];

static __device__ __forceinline__ void mma16(float c[4], const uint32_t a[4],
                                             uint32_t b0, uint32_t b1) {
    asm volatile(
        "mma.sync.aligned.m16n8k16.row.col.f32.f16.f16.f32 "
        "{%0,%1,%2,%3}, {%4,%5,%6,%7}, {%8,%9}, {%0,%1,%2,%3};\n"
        : "+f"(c[0]), "+f"(c[1]), "+f"(c[2]), "+f"(c[3])
        : "r"(a[0]), "r"(a[1]), "r"(a[2]), "r"(a[3]), "r"(b0), "r"(b1));
}

#define LDSM4(r, addr) \
    asm volatile("ldmatrix.sync.aligned.m8n8.x4.shared.b16 {%0,%1,%2,%3}, [%4];" \
                 : "=r"((r)[0]), "=r"((r)[1]), "=r"((r)[2]), "=r"((r)[3]) : "r"(addr))

static __device__ __forceinline__ void cpasync16(uint32_t dst, const void* src, int srcsize) {
    asm volatile("cp.async.cg.shared.global [%0], [%1], 16, %2;\n"
                 :: "r"(dst), "l"(src), "r"(srcsize));
}
#define CP_COMMIT() asm volatile("cp.async.commit_group;\n" ::: "memory")
#define CP_WAIT1()  asm volatile("cp.async.wait_group 1;\n" ::: "memory")

// ---------------------------------------------------------------------------
__global__ void noop_kernel() {}   // shifts ncu capture index onto phase_persistent

// ---------------------------------------------------------------------------
#define NX4 ((size_t)MI * In / 4)
#define NW4 ((size_t)G3n * In / 4)

__global__ void convert_all(const float* __restrict__ X,
                            const float* __restrict__ Wih_f, const float* __restrict__ Wih_b,
                            const float* __restrict__ Whh_f, const float* __restrict__ Whh_b)
{
    size_t i = (size_t)blockIdx.x * blockDim.x + threadIdx.x;
    const float* src; __half* dst; size_t off;
    if (i < NX4)                { src = X;     dst = g_X16;              off = i; }
    else if (i < NX4 + NW4)     { src = Wih_f; dst = g_Wih16;            off = i - NX4; }
    else if (i < NX4 + 2 * NW4) { src = Wih_b; dst = g_Wih16 + G3n * In; off = i - NX4 - NW4; }
    else if (i < NX4 + 3 * NW4) { src = Whh_f; dst = g_Whh16;            off = i - NX4 - 2 * NW4; }
    else if (i < NX4 + 4 * NW4) { src = Whh_b; dst = g_Whh16 + G3n * Hn; off = i - NX4 - 3 * NW4; }
    else return;
    float4 v = reinterpret_cast<const float4*>(src)[off];
    reinterpret_cast<__half2*>(dst)[2 * off]     = __floats2half2_rn(v.x, v.y);
    reinterpret_cast<__half2*>(dst)[2 * off + 1] = __floats2half2_rn(v.z, v.w);
}

// ---------------------------------------------------------------------------
// Input GEMM (R11, unchanged): resident Wih slice + 16 streamed m-tiles.
// ---------------------------------------------------------------------------
__global__ void __launch_bounds__(NT, 2)
input_gemm(const float* __restrict__ bih_f, const float* __restrict__ bhh_f,
           const float* __restrict__ bih_b, const float* __restrict__ bhh_b)
{
    extern __shared__ __half smh[];
    const uint32_t smA_u = (uint32_t)__cvta_generic_to_shared(smh);
    const uint32_t smB_u = smA_u + IG_B_OFF_H * 2;
    __half* smB = smh + IG_B_OFF_H;

    const int tid = threadIdx.x;
    const int warp = tid >> 5, lane = tid & 31;
    const int wm = warp >> 2, wn = warp & 3;
    const int lane8 = lane & 7, laneB = lane >> 3;

    const int c0 = blockIdx.x * 32;
    const size_t mbase = (size_t)blockIdx.y * (MT_PER_CTA * 128);
    const int dir = blockIdx.z;

    const float* bih = dir ? bih_b : bih_f;
    const float* bhh = dir ? bhh_b : bhh_f;

    {
        const __half* Wt = g_Wih16 + (size_t)dir * G3n * In;
        for (int idx = tid; idx < 96 * 32; idx += NT) {
            int row = idx >> 5, seg = (idx & 31) * 8;
            const float4 v = *reinterpret_cast<const float4*>(
                Wt + (size_t)((row >> 5) * Hn + c0 + (row & 31)) * In + seg);
            *reinterpret_cast<float4*>(smB + row * BSTH + seg) = v;
        }
    }
    __syncthreads();

    int a_off[4], b_off[3];
    #pragma unroll
    for (int mf = 0; mf < 4; mf++)
        a_off[mf] = (wm * 64 + mf * 16 + lane8 + 8 * (laneB & 1)) * ASTH + 8 * (lane >> 4);
    #pragma unroll
    for (int gt = 0; gt < 3; gt++)
        b_off[gt] = (gt * 32 + wn * 8 + lane8) * BSTH + 8 * laneB;

    const int aRow = tid >> 2, aChk = (tid & 3) * 8;
    const int g = lane >> 2, tk = lane & 3;
    const int colb = c0 + wn * 8 + 2 * tk;

    float bias[3][2];
    #pragma unroll
    for (int gt = 0; gt < 3; gt++) {
        int gcol = gt * Hn + colb;
        bias[gt][0] = bih[gcol]     + (gt < 2 ? bhh[gcol]     : 0.f);
        bias[gt][1] = bih[gcol + 1] + (gt < 2 ? bhh[gcol + 1] : 0.f);
    }

    __half* GXd = g_GX + (size_t)dir * MI * G3n;

    auto issueA = [&](int c) {
        const uint32_t base = smA_u + (c % 3) * (A_STAGE_H * 2);
        const int kco = (c & 7) * 32;
        const __half* s = g_X16 + (mbase + (size_t)(c >> 3) * 128 + aRow) * In + kco + aChk;
        cpasync16(base + (uint32_t)(aRow * ASTH + aChk) * 2, s, 16);
        cpasync16(base + (uint32_t)((aRow + 64) * ASTH + aChk) * 2, s + (size_t)64 * In, 16);
    };

    issueA(0); CP_COMMIT();
    issueA(1); CP_COMMIT();

    const int NCHUNK = MT_PER_CTA * 8;
    #pragma unroll 1
    for (int mt = 0; mt < MT_PER_CTA; mt++) {
        float acc[3][4][4];
        #pragma unroll
        for (int gt = 0; gt < 3; gt++)
            #pragma unroll
            for (int mi = 0; mi < 4; mi++)
                #pragma unroll
                for (int q = 0; q < 4; q++) acc[gt][mi][q] = 0.f;

        #pragma unroll 1
        for (int kc = 0; kc < 8; kc++) {
            const int c = mt * 8 + kc;
            CP_WAIT1();
            __syncthreads();
            if (c + 2 < NCHUNK) issueA(c + 2);
            CP_COMMIT();

            const uint32_t Ab = smA_u + (c % 3) * (A_STAGE_H * 2);

            uint32_t bfr[3][4];
            #pragma unroll
            for (int gt = 0; gt < 3; gt++)
                LDSM4(bfr[gt], smB_u + (uint32_t)(kc * 32 + b_off[gt]) * 2);
            #pragma unroll
            for (int ks = 0; ks < 2; ks++) {
                #pragma unroll
                for (int mf = 0; mf < 4; mf++) {
                    uint32_t af[4];
                    LDSM4(af, Ab + (a_off[mf] + 16 * ks) * 2);
                    #pragma unroll
                    for (int gt = 0; gt < 3; gt++)
                        mma16(acc[gt][mf], af, bfr[gt][2 * ks], bfr[gt][2 * ks + 1]);
                }
            }
        }

        const size_t m0 = mbase + (size_t)mt * 128;
        #pragma unroll
        for (int gt = 0; gt < 3; gt++) {
            int gcol = gt * Hn + colb;
            #pragma unroll
            for (int mi = 0; mi < 4; mi++) {
                size_t r0 = m0 + (size_t)(wm * 64 + mi * 16 + g);
                *reinterpret_cast<__half2*>(GXd + r0 * G3n + gcol) =
                    __floats2half2_rn(acc[gt][mi][0] + bias[gt][0], acc[gt][mi][1] + bias[gt][1]);
                *reinterpret_cast<__half2*>(GXd + (r0 + 8) * G3n + gcol) =
                    __floats2half2_rn(acc[gt][mi][2] + bias[gt][0], acc[gt][mi][3] + bias[gt][1]);
            }
        }
    }
}

// ---------------------------------------------------------------------------
static __device__ __forceinline__ float
row_scale(int rg, int j, int dir, const int* __restrict__ D)
{
    int blk = (rg >> 6) & 63, b = rg & 63;
    int t = dir ? (blk * TBn + TBn - 1 - j) : (blk * TBn + j);
    int m = dir ? ((t == SEQn - 1) ? 0 : D[(t + 1) * Bn + b]) : D[t * Bn + b];
    return 1.f - (float)m;
}

static __device__ __forceinline__ const __half*
row_src(int rg, int j, int rnd, int dir, const __half* Sread)
{
    if (j > 0) return Sread + (size_t)rg * Hn;
    if (rnd == 1) {
        int blk = (rg >> 6) & 63;
        int nb = dir ? blk + 1 : blk - 1;
        if (nb >= 0 && nb < NBLKn)
            return g_End16 + (size_t)(rg + (dir ? Bn : -Bn)) * Hn;
    }
    return nullptr;
}

static __device__ __forceinline__ void bar_sync(unsigned* cnt, unsigned* gen, unsigned n)
{
    __threadfence();
    __syncthreads();
    if (threadIdx.x == 0) {
        unsigned gv = *(volatile unsigned*)gen;
        unsigned c = atomicAdd(cnt, 1u);
        if (c == n - 1) {
            atomicExch(cnt, 0u);
            __threadfence();
            atomicAdd(gen, 1u);
        } else {
            while (*(volatile unsigned*)gen == gv) { __nanosleep(32); }
        }
    }
    __syncthreads();
    __threadfence();
}

// ---------------------------------------------------------------------------
// Persistent phase kernel (R11 structure) + per-step smem scale table and
// hoisted epilogue addressing (profile-driven: alu pipe was 20.9%).
// ---------------------------------------------------------------------------
__global__ void __launch_bounds__(NT, 2)
phase_persistent(const int* __restrict__ D,
                 const float* __restrict__ bhh_f, const float* __restrict__ bhh_b,
                 float* __restrict__ out)
{
    extern __shared__ __half smh[];
    const uint32_t smA_u = (uint32_t)__cvta_generic_to_shared(smh);
    const uint32_t smB_u = smA_u + PP_B_OFF_H * 2;
    const uint32_t smGX_u = smA_u + PP_GX_OFF_H * 2;
    __half* smB  = smh + PP_B_OFF_H;
    __half* smGX = smh + PP_GX_OFF_H;
    float* sWsc  = reinterpret_cast<float*>(smh + PP_SC_OFF_H);

    const int tid = threadIdx.x;
    const int warp = tid >> 5, lane = tid & 31;
    const int wm = warp >> 2, wn = warp & 3;
    const int lane8 = lane & 7, laneB = lane >> 3;

    const int cta = blockIdx.x;
    const int mpair = cta >> 3;
    const int c0 = (cta & 7) * 32;
    const int kch = cta & 7;
    const int m0base = mpair * 256;
    const int dir = m0base >> 12;

    const float* bhh = dir ? bhh_b : bhh_f;

    {
        const __half* Wt = g_Whh16 + (size_t)dir * G3n * Hn;
        for (int idx = tid; idx < 96 * 32; idx += NT) {
            int row = idx >> 5, seg = (idx & 31) * 8;
            const float4 v = *reinterpret_cast<const float4*>(
                Wt + (size_t)((row >> 5) * Hn + c0 + (row & 31)) * Hn + seg);
            *reinterpret_cast<float4*>(smB + row * BSTH + seg) = v;
        }
    }
    __syncthreads();

    int a_off[4], b_off[3];
    #pragma unroll
    for (int mf = 0; mf < 4; mf++)
        a_off[mf] = (wm * 64 + mf * 16 + lane8 + 8 * (laneB & 1)) * ASTH + 8 * (lane >> 4);
    #pragma unroll
    for (int gt = 0; gt < 3; gt++)
        b_off[gt] = (gt * 32 + wn * 8 + lane8) * BSTH + 8 * laneB;

    const int aRow = tid >> 2, aChk = (tid & 3) * 8;
    const int g = lane >> 2, tk = lane & 3;
    const int lc = wn * 8 + 2 * tk;
    const int colb = c0 + lc;
    const float2 bn2 = *reinterpret_cast<const float2*>(bhh + 2 * Hn + colb);

    const int gxrow = tid & 127;
    const int gxp0 = tid >> 7;
    const __half* GXd = g_GX + (size_t)dir * MI * G3n;

    for (int step = 0; step < 2 * TBn; step++) {
        const int rnd = step >> 5, j = step & 31, cur = step & 1;
        if (step == TBn)  bar_sync(&g_barc, &g_barg, NCTA);
        else if (step)    bar_sync(&g_lbc[mpair], &g_lbg[mpair], 8);

        // per-step scale table: next-state scale for row m0base+tid
        {
            int rg = m0base + tid;
            float w;
            if (j < TBn - 1) {
                w = row_scale(rg, j + 1, dir, D);
            } else if (rnd == 0) {
                int blk = (rg >> 6) & 63;
                int rgc = rg + (dir ? -Bn : Bn);
                bool valid = dir ? (blk > 0) : (blk < NBLKn - 1);
                w = valid ? row_scale(rgc, 0, dir, D) : 0.f;
            } else w = 0.f;
            sWsc[tid] = w;
        }

        __half* Swrite16 = g_State16[cur ^ 1];

        const __half* sA[2][2];
        const __half* gxsrc[2];
        #pragma unroll
        for (int mt = 0; mt < 2; mt++) {
            sA[mt][0] = row_src(m0base + mt * 128 + aRow,      j, rnd, dir, g_State16[cur]);
            sA[mt][1] = row_src(m0base + mt * 128 + aRow + 64, j, rnd, dir, g_State16[cur]);
            int rg = m0base + mt * 128 + gxrow;
            int blk = (rg >> 6) & 63, b = rg & 63;
            int t = dir ? (blk * TBn + TBn - 1 - j) : (blk * TBn + j);
            gxsrc[mt] = GXd + (size_t)(t * Bn + b) * G3n;
        }

        auto issueA = [&](int c) {
            const uint32_t base = smA_u + (c % 3) * (A_STAGE_H * 2);
            const int kco = (c & 7) * 32;
            const __half* s0 = sA[c >> 3][0];
            const __half* s1 = sA[c >> 3][1];
            const __half* dummy = g_Whh16;
            cpasync16(base + (uint32_t)(aRow * ASTH + aChk) * 2,
                      s0 ? s0 + kco + aChk : dummy, s0 ? 16 : 0);
            cpasync16(base + (uint32_t)((aRow + 64) * ASTH + aChk) * 2,
                      s1 ? s1 + kco + aChk : dummy, s1 ? 16 : 0);
        };
        auto issueGX = [&](int mt, int s) {
            int p = gxp0 + 2 * s;
            cpasync16(smGX_u + (uint32_t)(gxrow * GXSTH + p * 8) * 2,
                      gxsrc[mt] + (p >> 2) * Hn + c0 + (p & 3) * 8, 16);
        };

        issueA(0); issueGX(0, 0); CP_COMMIT();
        issueA(1); issueGX(0, 1); CP_COMMIT();

        #pragma unroll 1
        for (int mt = 0; mt < 2; mt++) {
            float acc[3][4][4];
            #pragma unroll
            for (int gt = 0; gt < 3; gt++)
                #pragma unroll
                for (int mi = 0; mi < 4; mi++)
                    #pragma unroll
                    for (int q = 0; q < 4; q++) acc[gt][mi][q] = 0.f;

            __half2 hureg[8];

            #pragma unroll 1
            for (int kc = 0; kc < 8; kc++) {
                const int c = mt * 8 + kc;
                CP_WAIT1();
                __syncthreads();
                if (c + 2 < 16) issueA(c + 2);
                if (c < 4) issueGX(0, c + 2);
                else if (c >= 8 && c < 14) issueGX(1, c - 8);
                CP_COMMIT();

                const uint32_t Ab = smA_u + (c % 3) * (A_STAGE_H * 2);
                const __half* Ah = smh + (c % 3) * A_STAGE_H;
                const uint32_t Bk = smB_u + (uint32_t)(kc * 32) * 2;

                if (kc == kch) {
                    #pragma unroll
                    for (int q = 0; q < 8; q++) {
                        int row = wm * 64 + (q >> 1) * 16 + g + 8 * (q & 1);
                        hureg[q] = *reinterpret_cast<const __half2*>(Ah + row * ASTH + lc);
                    }
                }

                uint32_t bfr[3][4];
                #pragma unroll
                for (int gt = 0; gt < 3; gt++) LDSM4(bfr[gt], Bk + b_off[gt] * 2);
                #pragma unroll
                for (int ks = 0; ks < 2; ks++) {
                    #pragma unroll
                    for (int mf = 0; mf < 4; mf++) {
                        uint32_t af[4];
                        LDSM4(af, Ab + (a_off[mf] + 16 * ks) * 2);
                        #pragma unroll
                        for (int gt = 0; gt < 3; gt++)
                            mma16(acc[gt][mf], af, bfr[gt][2 * ks], bfr[gt][2 * ks + 1]);
                    }
                }
            }

            // ---- epilogue (hoisted addressing; scale via smem table) ----
            const int m0 = m0base + mt * 128;
            const int rowB = wm * 64;
            const int blkE = ((m0 + rowB) >> 6) & 63;
            const int tE = dir ? (blkE * TBn + TBn - 1 - j) : (blkE * TBn + j);
            __half* dstS = (j < TBn - 1)
                ? (Swrite16 + (size_t)(m0 + rowB) * Hn + colb)
                : (rnd == 0 ? (g_End16 + (size_t)(m0 + rowB) * Hn + colb) : nullptr);
            float* outB = out + (size_t)(tE * Bn) * (2 * Hn) + dir * Hn + colb;
            const float* wscB = sWsc + mt * 128 + rowB;

            #pragma unroll
            for (int mi = 0; mi < 4; mi++) {
                #pragma unroll
                for (int p = 0; p < 2; p++) {
                    int b = mi * 16 + g + 8 * p;      // row within this 64-row block
                    int row = rowB + b;

                    float2 hu = __half22float2(hureg[mi * 2 + p]);

                    const __half* gxs = smGX + row * GXSTH;
                    float2 gr = __half22float2(*reinterpret_cast<const __half2*>(gxs + lc));
                    float2 gz = __half22float2(*reinterpret_cast<const __half2*>(gxs + 32 + lc));
                    float2 gn = __half22float2(*reinterpret_cast<const __half2*>(gxs + 64 + lc));

                    float rv0 = 1.f / (1.f + __expf(-(gr.x + acc[0][mi][2 * p])));
                    float rv1 = 1.f / (1.f + __expf(-(gr.y + acc[0][mi][2 * p + 1])));
                    float zv0 = 1.f / (1.f + __expf(-(gz.x + acc[1][mi][2 * p])));
                    float zv1 = 1.f / (1.f + __expf(-(gz.y + acc[1][mi][2 * p + 1])));
                    float nv0 = tanhf(gn.x + rv0 * (acc[2][mi][2 * p] + bn2.x));
                    float nv1 = tanhf(gn.y + rv1 * (acc[2][mi][2 * p + 1] + bn2.y));
                    float h0 = (1.f - zv0) * nv0 + zv0 * hu.x;
                    float h1 = (1.f - zv1) * nv1 + zv1 * hu.y;

                    if (dstS) {
                        float wsc = wscB[b];
                        *reinterpret_cast<__half2*>(dstS + (size_t)b * Hn) =
                            __floats2half2_rn(h0 * wsc, h1 * wsc);
                    }
                    if (rnd == 1)
                        *reinterpret_cast<float2*>(outB + (size_t)b * (2 * Hn)) =
                            make_float2(h0, h1);
                }
            }
        }
    }
}

// ---------------------------------------------------------------------------
extern "C" void kernel_launch(void* const* d_in, const int* in_sizes, int n_in,
                              void* d_out, int out_size)
{
    const float* X     = (const float*)d_in[0];
    const int*   D     = (const int*)d_in[1];
    const float* Wih_f = (const float*)d_in[2];
    const float* Whh_f = (const float*)d_in[3];
    const float* bih_f = (const float*)d_in[4];
    const float* bhh_f = (const float*)d_in[5];
    const float* Wih_b = (const float*)d_in[6];
    const float* Whh_b = (const float*)d_in[7];
    const float* bih_b = (const float*)d_in[8];
    const float* bhh_b = (const float*)d_in[9];
    float* out = (float*)d_out;

    cudaFuncSetAttribute(input_gemm, cudaFuncAttributeMaxDynamicSharedMemorySize, IG_SMEM);
    cudaFuncSetAttribute(phase_persistent, cudaFuncAttributeMaxDynamicSharedMemorySize, PP_SMEM);

    noop_kernel<<<1, 32>>>();

    const size_t ntot = NX4 + 4 * NW4;
    convert_all<<<(unsigned)((ntot + 255) / 256), 256>>>(X, Wih_f, Wih_b, Whh_f, Whh_b);

    input_gemm<<<dim3(Hn / 32, MI / (MT_PER_CTA * 128), 2), NT, IG_SMEM>>>(
        bih_f, bhh_f, bih_b, bhh_b);

    phase_persistent<<<NCTA, NT, PP_SMEM>>>(D, bhh_f, bhh_b, out);
}

// round 16
// speedup vs baseline: 1.4075x; 1.1539x over previous
#include <cuda_runtime.h>
#include <cuda_fp16.h>
#include <cstdint>
#include <cstddef>

#define SEQn 2048
#define Bn   64
#define In   256
#define Hn   256
#define G3n  768
#define TBn  32
#define NBLKn 64
#define MR   8192
#define MI   131072

#define NT   256       // 8 warps: 2(m) x 4(n)
#define ASTH 40
#define BSTH 264
#define GXSTH 104
#define A_STAGE_H (128 * ASTH)
#define NCTA 256
#define NMP  32
#define MT_PER_CTA 16

#define IG_B_OFF_H (3 * A_STAGE_H)
#define IG_SMEM ((IG_B_OFF_H + 96 * BSTH) * 2)

#define PP_B_OFF_H  (3 * A_STAGE_H)
#define PP_GX_OFF_H (PP_B_OFF_H + 96 * BSTH)
#define PP_SC_OFF_H (PP_GX_OFF_H + 128 * GXSTH)      // 256 floats = 512 halfs
#define PP_SMEM ((PP_SC_OFF_H + 512) * 2)            // 109056 B

__device__ __half g_GX[(size_t)2 * MI * G3n];
__device__ __half g_X16[(size_t)MI * In];
__device__ __half g_Wih16[(size_t)2 * G3n * In];
__device__ __half g_Whh16[(size_t)2 * G3n * Hn];
__device__ __half g_State16[2][(size_t)MR * Hn];
__device__ __half g_End16[(size_t)MR * Hn];
__device__ unsigned g_barc;
__device__ unsigned g_barg;
__device__ unsigned g_lbc[NMP];
__device__ unsigned g_lbg[NMP];

static __device__ __forceinline__ void mma16(float c[4], const uint32_t a[4],
                                             uint32_t b0, uint32_t b1) {
    asm volatile(
        "mma.sync.aligned.m16n8k16.row.col.f32.f16.f16.f32 "
        "{%0,%1,%2,%3}, {%4,%5,%6,%7}, {%8,%9}, {%0,%1,%2,%3};\n"
        : "+f"(c[0]), "+f"(c[1]), "+f"(c[2]), "+f"(c[3])
        : "r"(a[0]), "r"(a[1]), "r"(a[2]), "r"(a[3]), "r"(b0), "r"(b1));
}

#define LDSM4(r, addr) \
    asm volatile("ldmatrix.sync.aligned.m8n8.x4.shared.b16 {%0,%1,%2,%3}, [%4];" \
                 : "=r"((r)[0]), "=r"((r)[1]), "=r"((r)[2]), "=r"((r)[3]) : "r"(addr))

static __device__ __forceinline__ void cpasync16(uint32_t dst, const void* src, int srcsize) {
    asm volatile("cp.async.cg.shared.global [%0], [%1], 16, %2;\n"
                 :: "r"(dst), "l"(src), "r"(srcsize));
}
#define CP_COMMIT() asm volatile("cp.async.commit_group;\n" ::: "memory")
#define CP_WAIT1()  asm volatile("cp.async.wait_group 1;\n" ::: "memory")

// hardware tanh (MUFU.TANH, sm_75+): 1 op, max abs err ~4.9e-4
static __device__ __forceinline__ float tanh_ap(float x) {
    float r;
    asm("tanh.approx.f32 %0, %1;" : "=f"(r) : "f"(x));
    return r;
}
// sigmoid via tanh: 0.5*tanh(x/2)+0.5  (3 ops, 1 MUFU)
static __device__ __forceinline__ float sigm_ap(float x) {
    return fmaf(tanh_ap(0.5f * x), 0.5f, 0.5f);
}

// ---------------------------------------------------------------------------
__global__ void noop_kernel() {}   // shifts ncu capture index onto phase_persistent

// ---------------------------------------------------------------------------
#define NX4 ((size_t)MI * In / 4)
#define NW4 ((size_t)G3n * In / 4)

__global__ void convert_all(const float* __restrict__ X,
                            const float* __restrict__ Wih_f, const float* __restrict__ Wih_b,
                            const float* __restrict__ Whh_f, const float* __restrict__ Whh_b)
{
    size_t i = (size_t)blockIdx.x * blockDim.x + threadIdx.x;
    const float* src; __half* dst; size_t off;
    if (i < NX4)                { src = X;     dst = g_X16;              off = i; }
    else if (i < NX4 + NW4)     { src = Wih_f; dst = g_Wih16;            off = i - NX4; }
    else if (i < NX4 + 2 * NW4) { src = Wih_b; dst = g_Wih16 + G3n * In; off = i - NX4 - NW4; }
    else if (i < NX4 + 3 * NW4) { src = Whh_f; dst = g_Whh16;            off = i - NX4 - 2 * NW4; }
    else if (i < NX4 + 4 * NW4) { src = Whh_b; dst = g_Whh16 + G3n * Hn; off = i - NX4 - 3 * NW4; }
    else return;
    float4 v = reinterpret_cast<const float4*>(src)[off];
    reinterpret_cast<__half2*>(dst)[2 * off]     = __floats2half2_rn(v.x, v.y);
    reinterpret_cast<__half2*>(dst)[2 * off + 1] = __floats2half2_rn(v.z, v.w);
}

// ---------------------------------------------------------------------------
// Input GEMM (R11, unchanged): resident Wih slice + 16 streamed m-tiles.
// ---------------------------------------------------------------------------
__global__ void __launch_bounds__(NT, 2)
input_gemm(const float* __restrict__ bih_f, const float* __restrict__ bhh_f,
           const float* __restrict__ bih_b, const float* __restrict__ bhh_b)
{
    extern __shared__ __half smh[];
    const uint32_t smA_u = (uint32_t)__cvta_generic_to_shared(smh);
    const uint32_t smB_u = smA_u + IG_B_OFF_H * 2;
    __half* smB = smh + IG_B_OFF_H;

    const int tid = threadIdx.x;
    const int warp = tid >> 5, lane = tid & 31;
    const int wm = warp >> 2, wn = warp & 3;
    const int lane8 = lane & 7, laneB = lane >> 3;

    const int c0 = blockIdx.x * 32;
    const size_t mbase = (size_t)blockIdx.y * (MT_PER_CTA * 128);
    const int dir = blockIdx.z;

    const float* bih = dir ? bih_b : bih_f;
    const float* bhh = dir ? bhh_b : bhh_f;

    {
        const __half* Wt = g_Wih16 + (size_t)dir * G3n * In;
        for (int idx = tid; idx < 96 * 32; idx += NT) {
            int row = idx >> 5, seg = (idx & 31) * 8;
            const float4 v = *reinterpret_cast<const float4*>(
                Wt + (size_t)((row >> 5) * Hn + c0 + (row & 31)) * In + seg);
            *reinterpret_cast<float4*>(smB + row * BSTH + seg) = v;
        }
    }
    __syncthreads();

    int a_off[4], b_off[3];
    #pragma unroll
    for (int mf = 0; mf < 4; mf++)
        a_off[mf] = (wm * 64 + mf * 16 + lane8 + 8 * (laneB & 1)) * ASTH + 8 * (lane >> 4);
    #pragma unroll
    for (int gt = 0; gt < 3; gt++)
        b_off[gt] = (gt * 32 + wn * 8 + lane8) * BSTH + 8 * laneB;

    const int aRow = tid >> 2, aChk = (tid & 3) * 8;
    const int g = lane >> 2, tk = lane & 3;
    const int colb = c0 + wn * 8 + 2 * tk;

    float bias[3][2];
    #pragma unroll
    for (int gt = 0; gt < 3; gt++) {
        int gcol = gt * Hn + colb;
        bias[gt][0] = bih[gcol]     + (gt < 2 ? bhh[gcol]     : 0.f);
        bias[gt][1] = bih[gcol + 1] + (gt < 2 ? bhh[gcol + 1] : 0.f);
    }

    __half* GXd = g_GX + (size_t)dir * MI * G3n;

    auto issueA = [&](int c) {
        const uint32_t base = smA_u + (c % 3) * (A_STAGE_H * 2);
        const int kco = (c & 7) * 32;
        const __half* s = g_X16 + (mbase + (size_t)(c >> 3) * 128 + aRow) * In + kco + aChk;
        cpasync16(base + (uint32_t)(aRow * ASTH + aChk) * 2, s, 16);
        cpasync16(base + (uint32_t)((aRow + 64) * ASTH + aChk) * 2, s + (size_t)64 * In, 16);
    };

    issueA(0); CP_COMMIT();
    issueA(1); CP_COMMIT();

    const int NCHUNK = MT_PER_CTA * 8;
    #pragma unroll 1
    for (int mt = 0; mt < MT_PER_CTA; mt++) {
        float acc[3][4][4];
        #pragma unroll
        for (int gt = 0; gt < 3; gt++)
            #pragma unroll
            for (int mi = 0; mi < 4; mi++)
                #pragma unroll
                for (int q = 0; q < 4; q++) acc[gt][mi][q] = 0.f;

        #pragma unroll 1
        for (int kc = 0; kc < 8; kc++) {
            const int c = mt * 8 + kc;
            CP_WAIT1();
            __syncthreads();
            if (c + 2 < NCHUNK) issueA(c + 2);
            CP_COMMIT();

            const uint32_t Ab = smA_u + (c % 3) * (A_STAGE_H * 2);

            uint32_t bfr[3][4];
            #pragma unroll
            for (int gt = 0; gt < 3; gt++)
                LDSM4(bfr[gt], smB_u + (uint32_t)(kc * 32 + b_off[gt]) * 2);
            #pragma unroll
            for (int ks = 0; ks < 2; ks++) {
                #pragma unroll
                for (int mf = 0; mf < 4; mf++) {
                    uint32_t af[4];
                    LDSM4(af, Ab + (a_off[mf] + 16 * ks) * 2);
                    #pragma unroll
                    for (int gt = 0; gt < 3; gt++)
                        mma16(acc[gt][mf], af, bfr[gt][2 * ks], bfr[gt][2 * ks + 1]);
                }
            }
        }

        const size_t m0 = mbase + (size_t)mt * 128;
        #pragma unroll
        for (int gt = 0; gt < 3; gt++) {
            int gcol = gt * Hn + colb;
            #pragma unroll
            for (int mi = 0; mi < 4; mi++) {
                size_t r0 = m0 + (size_t)(wm * 64 + mi * 16 + g);
                *reinterpret_cast<__half2*>(GXd + r0 * G3n + gcol) =
                    __floats2half2_rn(acc[gt][mi][0] + bias[gt][0], acc[gt][mi][1] + bias[gt][1]);
                *reinterpret_cast<__half2*>(GXd + (r0 + 8) * G3n + gcol) =
                    __floats2half2_rn(acc[gt][mi][2] + bias[gt][0], acc[gt][mi][3] + bias[gt][1]);
            }
        }
    }
}

// ---------------------------------------------------------------------------
static __device__ __forceinline__ float
row_scale(int rg, int j, int dir, const int* __restrict__ D)
{
    int blk = (rg >> 6) & 63, b = rg & 63;
    int t = dir ? (blk * TBn + TBn - 1 - j) : (blk * TBn + j);
    int m = dir ? ((t == SEQn - 1) ? 0 : D[(t + 1) * Bn + b]) : D[t * Bn + b];
    return 1.f - (float)m;
}

static __device__ __forceinline__ const __half*
row_src(int rg, int j, int rnd, int dir, const __half* Sread)
{
    if (j > 0) return Sread + (size_t)rg * Hn;
    if (rnd == 1) {
        int blk = (rg >> 6) & 63;
        int nb = dir ? blk + 1 : blk - 1;
        if (nb >= 0 && nb < NBLKn)
            return g_End16 + (size_t)(rg + (dir ? Bn : -Bn)) * Hn;
    }
    return nullptr;
}

static __device__ __forceinline__ void bar_sync(unsigned* cnt, unsigned* gen, unsigned n)
{
    __threadfence();
    __syncthreads();
    if (threadIdx.x == 0) {
        unsigned gv = *(volatile unsigned*)gen;
        unsigned c = atomicAdd(cnt, 1u);
        if (c == n - 1) {
            atomicExch(cnt, 0u);
            __threadfence();
            atomicAdd(gen, 1u);
        } else {
            while (*(volatile unsigned*)gen == gv) { __nanosleep(32); }
        }
    }
    __syncthreads();
    __threadfence();
}

// ---------------------------------------------------------------------------
// Persistent phase kernel (R15 structure) + hardware tanh.approx epilogue
// (profile-driven: accurate tanhf/div dominated epilogue issue count).
// ---------------------------------------------------------------------------
__global__ void __launch_bounds__(NT, 2)
phase_persistent(const int* __restrict__ D,
                 const float* __restrict__ bhh_f, const float* __restrict__ bhh_b,
                 float* __restrict__ out)
{
    extern __shared__ __half smh[];
    const uint32_t smA_u = (uint32_t)__cvta_generic_to_shared(smh);
    const uint32_t smB_u = smA_u + PP_B_OFF_H * 2;
    const uint32_t smGX_u = smA_u + PP_GX_OFF_H * 2;
    __half* smB  = smh + PP_B_OFF_H;
    __half* smGX = smh + PP_GX_OFF_H;
    float* sWsc  = reinterpret_cast<float*>(smh + PP_SC_OFF_H);

    const int tid = threadIdx.x;
    const int warp = tid >> 5, lane = tid & 31;
    const int wm = warp >> 2, wn = warp & 3;
    const int lane8 = lane & 7, laneB = lane >> 3;

    const int cta = blockIdx.x;
    const int mpair = cta >> 3;
    const int c0 = (cta & 7) * 32;
    const int kch = cta & 7;
    const int m0base = mpair * 256;
    const int dir = m0base >> 12;

    const float* bhh = dir ? bhh_b : bhh_f;

    {
        const __half* Wt = g_Whh16 + (size_t)dir * G3n * Hn;
        for (int idx = tid; idx < 96 * 32; idx += NT) {
            int row = idx >> 5, seg = (idx & 31) * 8;
            const float4 v = *reinterpret_cast<const float4*>(
                Wt + (size_t)((row >> 5) * Hn + c0 + (row & 31)) * Hn + seg);
            *reinterpret_cast<float4*>(smB + row * BSTH + seg) = v;
        }
    }
    __syncthreads();

    int a_off[4], b_off[3];
    #pragma unroll
    for (int mf = 0; mf < 4; mf++)
        a_off[mf] = (wm * 64 + mf * 16 + lane8 + 8 * (laneB & 1)) * ASTH + 8 * (lane >> 4);
    #pragma unroll
    for (int gt = 0; gt < 3; gt++)
        b_off[gt] = (gt * 32 + wn * 8 + lane8) * BSTH + 8 * laneB;

    const int aRow = tid >> 2, aChk = (tid & 3) * 8;
    const int g = lane >> 2, tk = lane & 3;
    const int lc = wn * 8 + 2 * tk;
    const int colb = c0 + lc;
    const float2 bn2 = *reinterpret_cast<const float2*>(bhh + 2 * Hn + colb);

    const int gxrow = tid & 127;
    const int gxp0 = tid >> 7;
    const __half* GXd = g_GX + (size_t)dir * MI * G3n;

    for (int step = 0; step < 2 * TBn; step++) {
        const int rnd = step >> 5, j = step & 31, cur = step & 1;
        if (step == TBn)  bar_sync(&g_barc, &g_barg, NCTA);
        else if (step)    bar_sync(&g_lbc[mpair], &g_lbg[mpair], 8);

        // per-step scale table: next-state scale for row m0base+tid
        {
            int rg = m0base + tid;
            float w;
            if (j < TBn - 1) {
                w = row_scale(rg, j + 1, dir, D);
            } else if (rnd == 0) {
                int blk = (rg >> 6) & 63;
                int rgc = rg + (dir ? -Bn : Bn);
                bool valid = dir ? (blk > 0) : (blk < NBLKn - 1);
                w = valid ? row_scale(rgc, 0, dir, D) : 0.f;
            } else w = 0.f;
            sWsc[tid] = w;
        }

        __half* Swrite16 = g_State16[cur ^ 1];

        const __half* sA[2][2];
        const __half* gxsrc[2];
        #pragma unroll
        for (int mt = 0; mt < 2; mt++) {
            sA[mt][0] = row_src(m0base + mt * 128 + aRow,      j, rnd, dir, g_State16[cur]);
            sA[mt][1] = row_src(m0base + mt * 128 + aRow + 64, j, rnd, dir, g_State16[cur]);
            int rg = m0base + mt * 128 + gxrow;
            int blk = (rg >> 6) & 63, b = rg & 63;
            int t = dir ? (blk * TBn + TBn - 1 - j) : (blk * TBn + j);
            gxsrc[mt] = GXd + (size_t)(t * Bn + b) * G3n;
        }

        auto issueA = [&](int c) {
            const uint32_t base = smA_u + (c % 3) * (A_STAGE_H * 2);
            const int kco = (c & 7) * 32;
            const __half* s0 = sA[c >> 3][0];
            const __half* s1 = sA[c >> 3][1];
            const __half* dummy = g_Whh16;
            cpasync16(base + (uint32_t)(aRow * ASTH + aChk) * 2,
                      s0 ? s0 + kco + aChk : dummy, s0 ? 16 : 0);
            cpasync16(base + (uint32_t)((aRow + 64) * ASTH + aChk) * 2,
                      s1 ? s1 + kco + aChk : dummy, s1 ? 16 : 0);
        };
        auto issueGX = [&](int mt, int s) {
            int p = gxp0 + 2 * s;
            cpasync16(smGX_u + (uint32_t)(gxrow * GXSTH + p * 8) * 2,
                      gxsrc[mt] + (p >> 2) * Hn + c0 + (p & 3) * 8, 16);
        };

        issueA(0); issueGX(0, 0); CP_COMMIT();
        issueA(1); issueGX(0, 1); CP_COMMIT();

        #pragma unroll 1
        for (int mt = 0; mt < 2; mt++) {
            float acc[3][4][4];
            #pragma unroll
            for (int gt = 0; gt < 3; gt++)
                #pragma unroll
                for (int mi = 0; mi < 4; mi++)
                    #pragma unroll
                    for (int q = 0; q < 4; q++) acc[gt][mi][q] = 0.f;

            __half2 hureg[8];

            #pragma unroll 1
            for (int kc = 0; kc < 8; kc++) {
                const int c = mt * 8 + kc;
                CP_WAIT1();
                __syncthreads();
                if (c + 2 < 16) issueA(c + 2);
                if (c < 4) issueGX(0, c + 2);
                else if (c >= 8 && c < 14) issueGX(1, c - 8);
                CP_COMMIT();

                const uint32_t Ab = smA_u + (c % 3) * (A_STAGE_H * 2);
                const __half* Ah = smh + (c % 3) * A_STAGE_H;
                const uint32_t Bk = smB_u + (uint32_t)(kc * 32) * 2;

                if (kc == kch) {
                    #pragma unroll
                    for (int q = 0; q < 8; q++) {
                        int row = wm * 64 + (q >> 1) * 16 + g + 8 * (q & 1);
                        hureg[q] = *reinterpret_cast<const __half2*>(Ah + row * ASTH + lc);
                    }
                }

                uint32_t bfr[3][4];
                #pragma unroll
                for (int gt = 0; gt < 3; gt++) LDSM4(bfr[gt], Bk + b_off[gt] * 2);
                #pragma unroll
                for (int ks = 0; ks < 2; ks++) {
                    #pragma unroll
                    for (int mf = 0; mf < 4; mf++) {
                        uint32_t af[4];
                        LDSM4(af, Ab + (a_off[mf] + 16 * ks) * 2);
                        #pragma unroll
                        for (int gt = 0; gt < 3; gt++)
                            mma16(acc[gt][mf], af, bfr[gt][2 * ks], bfr[gt][2 * ks + 1]);
                    }
                }
            }

            // ---- epilogue (hoisted addressing; hw tanh.approx) ----
            const int m0 = m0base + mt * 128;
            const int rowB = wm * 64;
            const int blkE = ((m0 + rowB) >> 6) & 63;
            const int tE = dir ? (blkE * TBn + TBn - 1 - j) : (blkE * TBn + j);
            __half* dstS = (j < TBn - 1)
                ? (Swrite16 + (size_t)(m0 + rowB) * Hn + colb)
                : (rnd == 0 ? (g_End16 + (size_t)(m0 + rowB) * Hn + colb) : nullptr);
            float* outB = out + (size_t)(tE * Bn) * (2 * Hn) + dir * Hn + colb;
            const float* wscB = sWsc + mt * 128 + rowB;

            #pragma unroll
            for (int mi = 0; mi < 4; mi++) {
                #pragma unroll
                for (int p = 0; p < 2; p++) {
                    int b = mi * 16 + g + 8 * p;      // row within this 64-row block
                    int row = rowB + b;

                    float2 hu = __half22float2(hureg[mi * 2 + p]);

                    const __half* gxs = smGX + row * GXSTH;
                    float2 gr = __half22float2(*reinterpret_cast<const __half2*>(gxs + lc));
                    float2 gz = __half22float2(*reinterpret_cast<const __half2*>(gxs + 32 + lc));
                    float2 gn = __half22float2(*reinterpret_cast<const __half2*>(gxs + 64 + lc));

                    float rv0 = sigm_ap(gr.x + acc[0][mi][2 * p]);
                    float rv1 = sigm_ap(gr.y + acc[0][mi][2 * p + 1]);
                    float zv0 = sigm_ap(gz.x + acc[1][mi][2 * p]);
                    float zv1 = sigm_ap(gz.y + acc[1][mi][2 * p + 1]);
                    float nv0 = tanh_ap(fmaf(rv0, acc[2][mi][2 * p] + bn2.x, gn.x));
                    float nv1 = tanh_ap(fmaf(rv1, acc[2][mi][2 * p + 1] + bn2.y, gn.y));
                    float h0 = fmaf(zv0, hu.x - nv0, nv0);
                    float h1 = fmaf(zv1, hu.y - nv1, nv1);

                    if (dstS) {
                        float wsc = wscB[b];
                        *reinterpret_cast<__half2*>(dstS + (size_t)b * Hn) =
                            __floats2half2_rn(h0 * wsc, h1 * wsc);
                    }
                    if (rnd == 1)
                        *reinterpret_cast<float2*>(outB + (size_t)b * (2 * Hn)) =
                            make_float2(h0, h1);
                }
            }
        }
    }
}

// ---------------------------------------------------------------------------
extern "C" void kernel_launch(void* const* d_in, const int* in_sizes, int n_in,
                              void* d_out, int out_size)
{
    const float* X     = (const float*)d_in[0];
    const int*   D     = (const int*)d_in[1];
    const float* Wih_f = (const float*)d_in[2];
    const float* Whh_f = (const float*)d_in[3];
    const float* bih_f = (const float*)d_in[4];
    const float* bhh_f = (const float*)d_in[5];
    const float* Wih_b = (const float*)d_in[6];
    const float* Whh_b = (const float*)d_in[7];
    const float* bih_b = (const float*)d_in[8];
    const float* bhh_b = (const float*)d_in[9];
    float* out = (float*)d_out;

    cudaFuncSetAttribute(input_gemm, cudaFuncAttributeMaxDynamicSharedMemorySize, IG_SMEM);
    cudaFuncSetAttribute(phase_persistent, cudaFuncAttributeMaxDynamicSharedMemorySize, PP_SMEM);

    noop_kernel<<<1, 32>>>();

    const size_t ntot = NX4 + 4 * NW4;
    convert_all<<<(unsigned)((ntot + 255) / 256), 256>>>(X, Wih_f, Wih_b, Whh_f, Whh_b);

    input_gemm<<<dim3(Hn / 32, MI / (MT_PER_CTA * 128), 2), NT, IG_SMEM>>>(
        bih_f, bhh_f, bih_b, bhh_b);

    phase_persistent<<<NCTA, NT, PP_SMEM>>>(D, bhh_f, bhh_b, out);
}

// round 17
// speedup vs baseline: 1.4079x; 1.0002x over previous
#include <cuda_runtime.h>
#include <cuda_fp16.h>
#include <cstdint>
#include <cstddef>

#define SEQn 2048
#define Bn   64
#define In   256
#define Hn   256
#define G3n  768
#define TBn  32
#define NBLKn 64
#define MR   8192
#define MI   131072

#define NT   256       // 8 warps: 2(m) x 4(n)
#define ASTH 40
#define BSTH 264
#define GXSTH 104
#define A_STAGE_H (128 * ASTH)
#define NCTA 256
#define NMP  32
#define MT_PER_CTA 16

#define IG_B_OFF_H (3 * A_STAGE_H)
#define IG_SMEM ((IG_B_OFF_H + 96 * BSTH) * 2)

#define PP_B_OFF_H  (3 * A_STAGE_H)
#define PP_GX_OFF_H (PP_B_OFF_H + 96 * BSTH)
#define PP_SC_OFF_H (PP_GX_OFF_H + 128 * GXSTH)      // 256 floats = 512 halfs
#define PP_SMEM ((PP_SC_OFF_H + 512) * 2)            // 109056 B

__device__ __half g_GX[(size_t)2 * MI * G3n];
__device__ __half g_X16[(size_t)MI * In];
__device__ __half g_Wih16[(size_t)2 * G3n * In];
__device__ __half g_Whh16[(size_t)2 * G3n * Hn];
__device__ __half g_State16[2][(size_t)MR * Hn];
__device__ __half g_End16[(size_t)MR * Hn];
__device__ unsigned g_barc;
__device__ unsigned g_barg;
__device__ unsigned g_lbc[NMP];
__device__ unsigned g_lbg[NMP];

static __device__ __forceinline__ void mma16(float c[4], const uint32_t a[4],
                                             uint32_t b0, uint32_t b1) {
    asm volatile(
        "mma.sync.aligned.m16n8k16.row.col.f32.f16.f16.f32 "
        "{%0,%1,%2,%3}, {%4,%5,%6,%7}, {%8,%9}, {%0,%1,%2,%3};\n"
        : "+f"(c[0]), "+f"(c[1]), "+f"(c[2]), "+f"(c[3])
        : "r"(a[0]), "r"(a[1]), "r"(a[2]), "r"(a[3]), "r"(b0), "r"(b1));
}

#define LDSM4(r, addr) \
    asm volatile("ldmatrix.sync.aligned.m8n8.x4.shared.b16 {%0,%1,%2,%3}, [%4];" \
                 : "=r"((r)[0]), "=r"((r)[1]), "=r"((r)[2]), "=r"((r)[3]) : "r"(addr))

static __device__ __forceinline__ void cpasync16(uint32_t dst, const void* src, int srcsize) {
    asm volatile("cp.async.cg.shared.global [%0], [%1], 16, %2;\n"
                 :: "r"(dst), "l"(src), "r"(srcsize));
}
#define CP_COMMIT() asm volatile("cp.async.commit_group;\n" ::: "memory")
#define CP_WAIT1()  asm volatile("cp.async.wait_group 1;\n" ::: "memory")

// hardware tanh (MUFU.TANH, sm_75+): 1 op, max abs err ~4.9e-4
static __device__ __forceinline__ float tanh_ap(float x) {
    float r;
    asm("tanh.approx.f32 %0, %1;" : "=f"(r) : "f"(x));
    return r;
}
// sigmoid via tanh: 0.5*tanh(x/2)+0.5  (3 ops, 1 MUFU)
static __device__ __forceinline__ float sigm_ap(float x) {
    return fmaf(tanh_ap(0.5f * x), 0.5f, 0.5f);
}

// ---------------------------------------------------------------------------
__global__ void noop_kernel() {}   // shifts ncu capture index onto phase_persistent

// ---------------------------------------------------------------------------
#define NX4 ((size_t)MI * In / 4)
#define NW4 ((size_t)G3n * In / 4)

__global__ void convert_all(const float* __restrict__ X,
                            const float* __restrict__ Wih_f, const float* __restrict__ Wih_b,
                            const float* __restrict__ Whh_f, const float* __restrict__ Whh_b)
{
    size_t i = (size_t)blockIdx.x * blockDim.x + threadIdx.x;
    const float* src; __half* dst; size_t off;
    if (i < NX4)                { src = X;     dst = g_X16;              off = i; }
    else if (i < NX4 + NW4)     { src = Wih_f; dst = g_Wih16;            off = i - NX4; }
    else if (i < NX4 + 2 * NW4) { src = Wih_b; dst = g_Wih16 + G3n * In; off = i - NX4 - NW4; }
    else if (i < NX4 + 3 * NW4) { src = Whh_f; dst = g_Whh16;            off = i - NX4 - 2 * NW4; }
    else if (i < NX4 + 4 * NW4) { src = Whh_b; dst = g_Whh16 + G3n * Hn; off = i - NX4 - 3 * NW4; }
    else return;
    float4 v = reinterpret_cast<const float4*>(src)[off];
    reinterpret_cast<__half2*>(dst)[2 * off]     = __floats2half2_rn(v.x, v.y);
    reinterpret_cast<__half2*>(dst)[2 * off + 1] = __floats2half2_rn(v.z, v.w);
}

// ---------------------------------------------------------------------------
// Input GEMM (R11, unchanged): resident Wih slice + 16 streamed m-tiles.
// ---------------------------------------------------------------------------
__global__ void __launch_bounds__(NT, 2)
input_gemm(const float* __restrict__ bih_f, const float* __restrict__ bhh_f,
           const float* __restrict__ bih_b, const float* __restrict__ bhh_b)
{
    extern __shared__ __half smh[];
    const uint32_t smA_u = (uint32_t)__cvta_generic_to_shared(smh);
    const uint32_t smB_u = smA_u + IG_B_OFF_H * 2;
    __half* smB = smh + IG_B_OFF_H;

    const int tid = threadIdx.x;
    const int warp = tid >> 5, lane = tid & 31;
    const int wm = warp >> 2, wn = warp & 3;
    const int lane8 = lane & 7, laneB = lane >> 3;

    const int c0 = blockIdx.x * 32;
    const size_t mbase = (size_t)blockIdx.y * (MT_PER_CTA * 128);
    const int dir = blockIdx.z;

    const float* bih = dir ? bih_b : bih_f;
    const float* bhh = dir ? bhh_b : bhh_f;

    {
        const __half* Wt = g_Wih16 + (size_t)dir * G3n * In;
        for (int idx = tid; idx < 96 * 32; idx += NT) {
            int row = idx >> 5, seg = (idx & 31) * 8;
            const float4 v = *reinterpret_cast<const float4*>(
                Wt + (size_t)((row >> 5) * Hn + c0 + (row & 31)) * In + seg);
            *reinterpret_cast<float4*>(smB + row * BSTH + seg) = v;
        }
    }
    __syncthreads();

    int a_off[4], b_off[3];
    #pragma unroll
    for (int mf = 0; mf < 4; mf++)
        a_off[mf] = (wm * 64 + mf * 16 + lane8 + 8 * (laneB & 1)) * ASTH + 8 * (lane >> 4);
    #pragma unroll
    for (int gt = 0; gt < 3; gt++)
        b_off[gt] = (gt * 32 + wn * 8 + lane8) * BSTH + 8 * laneB;

    const int aRow = tid >> 2, aChk = (tid & 3) * 8;
    const int g = lane >> 2, tk = lane & 3;
    const int colb = c0 + wn * 8 + 2 * tk;

    float bias[3][2];
    #pragma unroll
    for (int gt = 0; gt < 3; gt++) {
        int gcol = gt * Hn + colb;
        bias[gt][0] = bih[gcol]     + (gt < 2 ? bhh[gcol]     : 0.f);
        bias[gt][1] = bih[gcol + 1] + (gt < 2 ? bhh[gcol + 1] : 0.f);
    }

    __half* GXd = g_GX + (size_t)dir * MI * G3n;

    auto issueA = [&](int c) {
        const uint32_t base = smA_u + (c % 3) * (A_STAGE_H * 2);
        const int kco = (c & 7) * 32;
        const __half* s = g_X16 + (mbase + (size_t)(c >> 3) * 128 + aRow) * In + kco + aChk;
        cpasync16(base + (uint32_t)(aRow * ASTH + aChk) * 2, s, 16);
        cpasync16(base + (uint32_t)((aRow + 64) * ASTH + aChk) * 2, s + (size_t)64 * In, 16);
    };

    issueA(0); CP_COMMIT();
    issueA(1); CP_COMMIT();

    const int NCHUNK = MT_PER_CTA * 8;
    #pragma unroll 1
    for (int mt = 0; mt < MT_PER_CTA; mt++) {
        float acc[3][4][4];
        #pragma unroll
        for (int gt = 0; gt < 3; gt++)
            #pragma unroll
            for (int mi = 0; mi < 4; mi++)
                #pragma unroll
                for (int q = 0; q < 4; q++) acc[gt][mi][q] = 0.f;

        #pragma unroll 1
        for (int kc = 0; kc < 8; kc++) {
            const int c = mt * 8 + kc;
            CP_WAIT1();
            __syncthreads();
            if (c + 2 < NCHUNK) issueA(c + 2);
            CP_COMMIT();

            const uint32_t Ab = smA_u + (c % 3) * (A_STAGE_H * 2);

            uint32_t bfr[3][4];
            #pragma unroll
            for (int gt = 0; gt < 3; gt++)
                LDSM4(bfr[gt], smB_u + (uint32_t)(kc * 32 + b_off[gt]) * 2);
            #pragma unroll
            for (int ks = 0; ks < 2; ks++) {
                #pragma unroll
                for (int mf = 0; mf < 4; mf++) {
                    uint32_t af[4];
                    LDSM4(af, Ab + (a_off[mf] + 16 * ks) * 2);
                    #pragma unroll
                    for (int gt = 0; gt < 3; gt++)
                        mma16(acc[gt][mf], af, bfr[gt][2 * ks], bfr[gt][2 * ks + 1]);
                }
            }
        }

        const size_t m0 = mbase + (size_t)mt * 128;
        #pragma unroll
        for (int gt = 0; gt < 3; gt++) {
            int gcol = gt * Hn + colb;
            #pragma unroll
            for (int mi = 0; mi < 4; mi++) {
                size_t r0 = m0 + (size_t)(wm * 64 + mi * 16 + g);
                *reinterpret_cast<__half2*>(GXd + r0 * G3n + gcol) =
                    __floats2half2_rn(acc[gt][mi][0] + bias[gt][0], acc[gt][mi][1] + bias[gt][1]);
                *reinterpret_cast<__half2*>(GXd + (r0 + 8) * G3n + gcol) =
                    __floats2half2_rn(acc[gt][mi][2] + bias[gt][0], acc[gt][mi][3] + bias[gt][1]);
            }
        }
    }
}

// ---------------------------------------------------------------------------
static __device__ __forceinline__ float
row_scale(int rg, int j, int dir, const int* __restrict__ D)
{
    int blk = (rg >> 6) & 63, b = rg & 63;
    int t = dir ? (blk * TBn + TBn - 1 - j) : (blk * TBn + j);
    int m = dir ? ((t == SEQn - 1) ? 0 : D[(t + 1) * Bn + b]) : D[t * Bn + b];
    return 1.f - (float)m;
}

static __device__ __forceinline__ const __half*
row_src(int rg, int j, int rnd, int dir, const __half* Sread)
{
    if (j > 0) return Sread + (size_t)rg * Hn;
    if (rnd == 1) {
        int blk = (rg >> 6) & 63;
        int nb = dir ? blk + 1 : blk - 1;
        if (nb >= 0 && nb < NBLKn)
            return g_End16 + (size_t)(rg + (dir ? Bn : -Bn)) * Hn;
    }
    return nullptr;
}

static __device__ __forceinline__ void bar_sync(unsigned* cnt, unsigned* gen, unsigned n)
{
    __threadfence();
    __syncthreads();
    if (threadIdx.x == 0) {
        unsigned gv = *(volatile unsigned*)gen;
        unsigned c = atomicAdd(cnt, 1u);
        if (c == n - 1) {
            atomicExch(cnt, 0u);
            __threadfence();
            atomicAdd(gen, 1u);
        } else {
            while (*(volatile unsigned*)gen == gv) { __nanosleep(32); }
        }
    }
    __syncthreads();
    __threadfence();
}

// ---------------------------------------------------------------------------
// Persistent phase kernel (R15 structure) + hardware tanh.approx epilogue
// (profile-driven: accurate tanhf/div dominated epilogue issue count).
// ---------------------------------------------------------------------------
__global__ void __launch_bounds__(NT, 2)
phase_persistent(const int* __restrict__ D,
                 const float* __restrict__ bhh_f, const float* __restrict__ bhh_b,
                 float* __restrict__ out)
{
    extern __shared__ __half smh[];
    const uint32_t smA_u = (uint32_t)__cvta_generic_to_shared(smh);
    const uint32_t smB_u = smA_u + PP_B_OFF_H * 2;
    const uint32_t smGX_u = smA_u + PP_GX_OFF_H * 2;
    __half* smB  = smh + PP_B_OFF_H;
    __half* smGX = smh + PP_GX_OFF_H;
    float* sWsc  = reinterpret_cast<float*>(smh + PP_SC_OFF_H);

    const int tid = threadIdx.x;
    const int warp = tid >> 5, lane = tid & 31;
    const int wm = warp >> 2, wn = warp & 3;
    const int lane8 = lane & 7, laneB = lane >> 3;

    const int cta = blockIdx.x;
    const int mpair = cta >> 3;
    const int c0 = (cta & 7) * 32;
    const int kch = cta & 7;
    const int m0base = mpair * 256;
    const int dir = m0base >> 12;

    const float* bhh = dir ? bhh_b : bhh_f;

    {
        const __half* Wt = g_Whh16 + (size_t)dir * G3n * Hn;
        for (int idx = tid; idx < 96 * 32; idx += NT) {
            int row = idx >> 5, seg = (idx & 31) * 8;
            const float4 v = *reinterpret_cast<const float4*>(
                Wt + (size_t)((row >> 5) * Hn + c0 + (row & 31)) * Hn + seg);
            *reinterpret_cast<float4*>(smB + row * BSTH + seg) = v;
        }
    }
    __syncthreads();

    int a_off[4], b_off[3];
    #pragma unroll
    for (int mf = 0; mf < 4; mf++)
        a_off[mf] = (wm * 64 + mf * 16 + lane8 + 8 * (laneB & 1)) * ASTH + 8 * (lane >> 4);
    #pragma unroll
    for (int gt = 0; gt < 3; gt++)
        b_off[gt] = (gt * 32 + wn * 8 + lane8) * BSTH + 8 * laneB;

    const int aRow = tid >> 2, aChk = (tid & 3) * 8;
    const int g = lane >> 2, tk = lane & 3;
    const int lc = wn * 8 + 2 * tk;
    const int colb = c0 + lc;
    const float2 bn2 = *reinterpret_cast<const float2*>(bhh + 2 * Hn + colb);

    const int gxrow = tid & 127;
    const int gxp0 = tid >> 7;
    const __half* GXd = g_GX + (size_t)dir * MI * G3n;

    for (int step = 0; step < 2 * TBn; step++) {
        const int rnd = step >> 5, j = step & 31, cur = step & 1;
        if (step == TBn)  bar_sync(&g_barc, &g_barg, NCTA);
        else if (step)    bar_sync(&g_lbc[mpair], &g_lbg[mpair], 8);

        // per-step scale table: next-state scale for row m0base+tid
        {
            int rg = m0base + tid;
            float w;
            if (j < TBn - 1) {
                w = row_scale(rg, j + 1, dir, D);
            } else if (rnd == 0) {
                int blk = (rg >> 6) & 63;
                int rgc = rg + (dir ? -Bn : Bn);
                bool valid = dir ? (blk > 0) : (blk < NBLKn - 1);
                w = valid ? row_scale(rgc, 0, dir, D) : 0.f;
            } else w = 0.f;
            sWsc[tid] = w;
        }

        __half* Swrite16 = g_State16[cur ^ 1];

        const __half* sA[2][2];
        const __half* gxsrc[2];
        #pragma unroll
        for (int mt = 0; mt < 2; mt++) {
            sA[mt][0] = row_src(m0base + mt * 128 + aRow,      j, rnd, dir, g_State16[cur]);
            sA[mt][1] = row_src(m0base + mt * 128 + aRow + 64, j, rnd, dir, g_State16[cur]);
            int rg = m0base + mt * 128 + gxrow;
            int blk = (rg >> 6) & 63, b = rg & 63;
            int t = dir ? (blk * TBn + TBn - 1 - j) : (blk * TBn + j);
            gxsrc[mt] = GXd + (size_t)(t * Bn + b) * G3n;
        }

        auto issueA = [&](int c) {
            const uint32_t base = smA_u + (c % 3) * (A_STAGE_H * 2);
            const int kco = (c & 7) * 32;
            const __half* s0 = sA[c >> 3][0];
            const __half* s1 = sA[c >> 3][1];
            const __half* dummy = g_Whh16;
            cpasync16(base + (uint32_t)(aRow * ASTH + aChk) * 2,
                      s0 ? s0 + kco + aChk : dummy, s0 ? 16 : 0);
            cpasync16(base + (uint32_t)((aRow + 64) * ASTH + aChk) * 2,
                      s1 ? s1 + kco + aChk : dummy, s1 ? 16 : 0);
        };
        auto issueGX = [&](int mt, int s) {
            int p = gxp0 + 2 * s;
            cpasync16(smGX_u + (uint32_t)(gxrow * GXSTH + p * 8) * 2,
                      gxsrc[mt] + (p >> 2) * Hn + c0 + (p & 3) * 8, 16);
        };

        issueA(0); issueGX(0, 0); CP_COMMIT();
        issueA(1); issueGX(0, 1); CP_COMMIT();

        #pragma unroll 1
        for (int mt = 0; mt < 2; mt++) {
            float acc[3][4][4];
            #pragma unroll
            for (int gt = 0; gt < 3; gt++)
                #pragma unroll
                for (int mi = 0; mi < 4; mi++)
                    #pragma unroll
                    for (int q = 0; q < 4; q++) acc[gt][mi][q] = 0.f;

            __half2 hureg[8];

            #pragma unroll 1
            for (int kc = 0; kc < 8; kc++) {
                const int c = mt * 8 + kc;
                CP_WAIT1();
                __syncthreads();
                if (c + 2 < 16) issueA(c + 2);
                if (c < 4) issueGX(0, c + 2);
                else if (c >= 8 && c < 14) issueGX(1, c - 8);
                CP_COMMIT();

                const uint32_t Ab = smA_u + (c % 3) * (A_STAGE_H * 2);
                const __half* Ah = smh + (c % 3) * A_STAGE_H;
                const uint32_t Bk = smB_u + (uint32_t)(kc * 32) * 2;

                if (kc == kch) {
                    #pragma unroll
                    for (int q = 0; q < 8; q++) {
                        int row = wm * 64 + (q >> 1) * 16 + g + 8 * (q & 1);
                        hureg[q] = *reinterpret_cast<const __half2*>(Ah + row * ASTH + lc);
                    }
                }

                uint32_t bfr[3][4];
                #pragma unroll
                for (int gt = 0; gt < 3; gt++) LDSM4(bfr[gt], Bk + b_off[gt] * 2);
                #pragma unroll
                for (int ks = 0; ks < 2; ks++) {
                    #pragma unroll
                    for (int mf = 0; mf < 4; mf++) {
                        uint32_t af[4];
                        LDSM4(af, Ab + (a_off[mf] + 16 * ks) * 2);
                        #pragma unroll
                        for (int gt = 0; gt < 3; gt++)
                            mma16(acc[gt][mf], af, bfr[gt][2 * ks], bfr[gt][2 * ks + 1]);
                    }
                }
            }

            // ---- epilogue (hoisted addressing; hw tanh.approx) ----
            const int m0 = m0base + mt * 128;
            const int rowB = wm * 64;
            const int blkE = ((m0 + rowB) >> 6) & 63;
            const int tE = dir ? (blkE * TBn + TBn - 1 - j) : (blkE * TBn + j);
            __half* dstS = (j < TBn - 1)
                ? (Swrite16 + (size_t)(m0 + rowB) * Hn + colb)
                : (rnd == 0 ? (g_End16 + (size_t)(m0 + rowB) * Hn + colb) : nullptr);
            float* outB = out + (size_t)(tE * Bn) * (2 * Hn) + dir * Hn + colb;
            const float* wscB = sWsc + mt * 128 + rowB;

            #pragma unroll
            for (int mi = 0; mi < 4; mi++) {
                #pragma unroll
                for (int p = 0; p < 2; p++) {
                    int b = mi * 16 + g + 8 * p;      // row within this 64-row block
                    int row = rowB + b;

                    float2 hu = __half22float2(hureg[mi * 2 + p]);

                    const __half* gxs = smGX + row * GXSTH;
                    float2 gr = __half22float2(*reinterpret_cast<const __half2*>(gxs + lc));
                    float2 gz = __half22float2(*reinterpret_cast<const __half2*>(gxs + 32 + lc));
                    float2 gn = __half22float2(*reinterpret_cast<const __half2*>(gxs + 64 + lc));

                    float rv0 = sigm_ap(gr.x + acc[0][mi][2 * p]);
                    float rv1 = sigm_ap(gr.y + acc[0][mi][2 * p + 1]);
                    float zv0 = sigm_ap(gz.x + acc[1][mi][2 * p]);
                    float zv1 = sigm_ap(gz.y + acc[1][mi][2 * p + 1]);
                    float nv0 = tanh_ap(fmaf(rv0, acc[2][mi][2 * p] + bn2.x, gn.x));
                    float nv1 = tanh_ap(fmaf(rv1, acc[2][mi][2 * p + 1] + bn2.y, gn.y));
                    float h0 = fmaf(zv0, hu.x - nv0, nv0);
                    float h1 = fmaf(zv1, hu.y - nv1, nv1);

                    if (dstS) {
                        float wsc = wscB[b];
                        *reinterpret_cast<__half2*>(dstS + (size_t)b * Hn) =
                            __floats2half2_rn(h0 * wsc, h1 * wsc);
                    }
                    if (rnd == 1)
                        *reinterpret_cast<float2*>(outB + (size_t)b * (2 * Hn)) =
                            make_float2(h0, h1);
                }
            }
        }
    }
}

// ---------------------------------------------------------------------------
extern "C" void kernel_launch(void* const* d_in, const int* in_sizes, int n_in,
                              void* d_out, int out_size)
{
    const float* X     = (const float*)d_in[0];
    const int*   D     = (const int*)d_in[1];
    const float* Wih_f = (const float*)d_in[2];
    const float* Whh_f = (const float*)d_in[3];
    const float* bih_f = (const float*)d_in[4];
    const float* bhh_f = (const float*)d_in[5];
    const float* Wih_b = (const float*)d_in[6];
    const float* Whh_b = (const float*)d_in[7];
    const float* bih_b = (const float*)d_in[8];
    const float* bhh_b = (const float*)d_in[9];
    float* out = (float*)d_out;

    cudaFuncSetAttribute(input_gemm, cudaFuncAttributeMaxDynamicSharedMemorySize, IG_SMEM);
    cudaFuncSetAttribute(phase_persistent, cudaFuncAttributeMaxDynamicSharedMemorySize, PP_SMEM);

    noop_kernel<<<1, 32>>>();

    const size_t ntot = NX4 + 4 * NW4;
    convert_all<<<(unsigned)((ntot + 255) / 256), 256>>>(X, Wih_f, Wih_b, Whh_f, Whh_b);

    input_gemm<<<dim3(Hn / 32, MI / (MT_PER_CTA * 128), 2), NT, IG_SMEM>>>(
        bih_f, bhh_f, bih_b, bhh_b);

    phase_persistent<<<NCTA, NT, PP_SMEM>>>(D, bhh_f, bhh_b, out);
}